// round 12
// baseline (speedup 1.0000x reference)
#include <cuda_runtime.h>
#include <cuda_bf16.h>
#include <math.h>
#include <stdint.h>

#define Bn   8
#define Cn   64
#define Nn   4096
#define On   64
#define KNN  20
#define SLOPE 0.2f
#define EPSC  1e-5f

// warp-level bf16 MMA (sm_80+ PTX, compiles for baseline sm_103 — tcgen05 does NOT)
#define MMA_BF16(c, a, b0, b1) \
    asm volatile("mma.sync.aligned.m16n8k16.row.col.f32.bf16.bf16.f32 " \
        "{%0,%1,%2,%3}, {%4,%5,%6,%7}, {%8,%9}, {%0,%1,%2,%3};" \
        : "+f"((c)[0]), "+f"((c)[1]), "+f"((c)[2]), "+f"((c)[3]) \
        : "r"((a)[0]), "r"((a)[1]), "r"((a)[2]), "r"((a)[3]), "r"(b0), "r"(b1))

// ---------------- device scratch ----------------
__device__ float g_xx[Bn * Nn];
__device__ int   g_idx[Bn * Nn * KNN];
__device__ float g_u[Bn * Nn * On];
__device__ float g_v[Bn * Nn * On];
__device__ float g_sel[Bn * Nn * On];
__device__ float g_sum[On];
__device__ float g_sumsq[On];
__device__ float g_cA[On];
__device__ float g_cB[On];
__device__ __nv_bfloat16 g_s[Bn * Nn * 192];   // [b][n][3 chunks x 64] bf16 splits

// ---------------- K1: squared norms ----------------
__global__ void xx_kernel(const float* __restrict__ x) {
    int i = blockIdx.x * 256 + threadIdx.x;
    int b = i >> 12;
    int n = i & (Nn - 1);
    const float* xp = x + b * Cn * Nn + n;
    float s = 0.f;
#pragma unroll
    for (int c = 0; c < Cn; ++c) { float v = xp[c * Nn]; s = fmaf(v, v, s); }
    g_xx[i] = s;
}

// ---------------- K1b: bf16x3 split + transpose ----------------
// out row [n]: [b0(64 bf16) | b1 | b2] = 384 B. b0+b1+b2 reconstructs x to ~2^-35.
__global__ void split_kernel(const float* __restrict__ x) {
    __shared__ alignas(16) __nv_bfloat16 sb0[64 * 72];
    __shared__ alignas(16) __nv_bfloat16 sb1[64 * 72];
    __shared__ alignas(16) __nv_bfloat16 sb2[64 * 72];

    int t = threadIdx.x;
    int b = blockIdx.x >> 6;
    int n0 = (blockIdx.x & 63) * 64;

#pragma unroll
    for (int j = 0; j < 16; ++j) {
        int idx = j * 256 + t;
        int c = idx >> 6, n = idx & 63;
        float v = x[b * Cn * Nn + c * Nn + n0 + n];
        __nv_bfloat16 h0 = __float2bfloat16(v);
        float f0 = __bfloat162float(h0);
        __nv_bfloat16 h1 = __float2bfloat16(v - f0);
        float f1 = __bfloat162float(h1);
        __nv_bfloat16 h2 = __float2bfloat16(v - f0 - f1);
        sb0[n * 72 + c] = h0;
        sb1[n * 72 + c] = h1;
        sb2[n * 72 + c] = h2;
    }
    __syncthreads();

    uint4* g4 = (uint4*)g_s;
#pragma unroll
    for (int j = 0; j < 6; ++j) {
        int idx = j * 256 + t;
        int r = idx / 24, u = idx % 24;
        int ch = u >> 3, c8 = (u & 7) * 8;
        const __nv_bfloat16* src = (ch == 0) ? sb0 : (ch == 1) ? sb1 : sb2;
        g4[(b * Nn + n0 + r) * 24 + u] = *(const uint4*)(src + r * 72 + c8);
    }
}

// ---------------- K2: mma.sync distance GEMM + top-K ----------------
// CTA: 64 queries, 256 threads (8 warps), 64 col-tiles of 64 candidates.
// Warp (wid&3) owns rows (wid&3)*16; wid>=4 owns cols 32..63 (n-tiles 4..7).
// 6-product bf16 stack per k16 step: A0B0,A1B1,A0B1,A1B0,A0B2,A2B0.
// Scores staged owner-major (owner=2q+colhalf, stride 36) minus 0.5*xx;
// scan/threshold/insert identical to the proven R10 path.
#define QT 64
#define CT 64
#define SROW 400                       // smem row bytes: 384 data + 16 pad (conflict-free frags)

#define OFF_A    0                     // 64*400 = 25600
#define OFF_B    25600                 // 25600 -> 51200
#define OFF_SC   51200                 // 256*36*4 = 36864 -> 88064
#define OFF_HXX  88064                 // 64*4 -> 88320 (+pad)
#define OFF_MINV 88320                 // 256*4 -> 89344
#define SMEM_KNN 89600
#define OFF_MV   0                     // post-loop alias of A/B region
#define OFF_MI   20480

__global__ void __launch_bounds__(256, 2) knn_kernel() {
    extern __shared__ char sm[];
    float* s_sc   = (float*)(sm + OFF_SC);
    float* s_hxx  = (float*)(sm + OFF_HXX);
    float* s_minv = (float*)(sm + OFF_MINV);
    float* s_mv   = (float*)(sm + OFF_MV);
    int*   s_mi   = (int*)  (sm + OFF_MI);

    int t = threadIdx.x, wid = t >> 5, lane = t & 31;
    int g = lane >> 2, q4 = lane & 3;
    int b = blockIdx.x >> 6;
    int n0 = (blockIdx.x & 63) * QT;

    const uint4* gs4 = (const uint4*)g_s;
    // resident A tile: 64 query rows x 24 uint4
#pragma unroll
    for (int j = 0; j < 6; ++j) {
        int idx = j * 256 + t;
        int r = idx / 24, u = idx % 24;
        *(uint4*)(sm + OFF_A + r * SROW + u * 16) = gs4[(b * Nn + n0 + r) * 24 + u];
    }
    s_minv[t] = -INFINITY;

    int wrow = (wid & 3) * 16;
    int ntb  = (wid >= 4) ? 4 : 0;

    float vals[KNN];
    int   idxs[KNN];
#pragma unroll
    for (int j = 0; j < KNN; ++j) { vals[j] = -INFINITY; idxs[j] = 0x7fffffff; }

    int sbase = t * 36;
    int thrb  = t & ~1;
    int mhalf = (t & 1) * 32;

    for (int ti = 0; ti < Nn / CT; ++ti) {
        int m0 = ti * CT;
        // load B tile + half-norms
#pragma unroll
        for (int j = 0; j < 6; ++j) {
            int idx = j * 256 + t;
            int r = idx / 24, u = idx % 24;
            *(uint4*)(sm + OFF_B + r * SROW + u * 16) = gs4[(b * Nn + m0 + r) * 24 + u];
        }
        if (t < CT) s_hxx[t] = 0.5f * g_xx[b * Nn + m0 + t];
        __syncthreads();   // (1) B/hxx ready; prev scan done reading s_sc

        float acc[4][4];
#pragma unroll
        for (int nt = 0; nt < 4; ++nt)
#pragma unroll
            for (int e = 0; e < 4; ++e) acc[nt][e] = 0.f;

#pragma unroll
        for (int ks = 0; ks < 4; ++ks) {
            uint32_t af[3][4];
#pragma unroll
            for (int ch = 0; ch < 3; ++ch) {
                const char* ab = sm + OFF_A + ch * 128 + ks * 32 + q4 * 4;
                af[ch][0] = *(const uint32_t*)(ab + (wrow + g) * SROW);
                af[ch][1] = *(const uint32_t*)(ab + (wrow + g + 8) * SROW);
                af[ch][2] = *(const uint32_t*)(ab + (wrow + g) * SROW + 16);
                af[ch][3] = *(const uint32_t*)(ab + (wrow + g + 8) * SROW + 16);
            }
#pragma unroll
            for (int nt = 0; nt < 4; ++nt) {
                const char* bb = sm + OFF_B + ((ntb + nt) * 8 + g) * SROW + ks * 32 + q4 * 4;
                uint32_t b0c0 = *(const uint32_t*)(bb);
                uint32_t b1c0 = *(const uint32_t*)(bb + 16);
                uint32_t b0c1 = *(const uint32_t*)(bb + 128);
                uint32_t b1c1 = *(const uint32_t*)(bb + 144);
                uint32_t b0c2 = *(const uint32_t*)(bb + 256);
                uint32_t b1c2 = *(const uint32_t*)(bb + 272);
                MMA_BF16(acc[nt], af[0], b0c0, b1c0);   // b0*b0
                MMA_BF16(acc[nt], af[1], b0c1, b1c1);   // b1*b1
                MMA_BF16(acc[nt], af[0], b0c1, b1c1);   // b0*b1
                MMA_BF16(acc[nt], af[1], b0c0, b1c0);   // b1*b0
                MMA_BF16(acc[nt], af[0], b0c2, b1c2);   // b0*b2
                MMA_BF16(acc[nt], af[2], b0c0, b1c0);   // b2*b0
            }
        }

        // stage: score = I - 0.5*xx_m, owner-major skew-36
#pragma unroll
        for (int nt = 0; nt < 4; ++nt) {
            int cg = (ntb + nt) * 8 + 2 * q4;
            float2 hx = *(const float2*)(s_hxx + cg);
            int hc = cg >> 5, sl = cg & 31;
            int q0 = wrow + g, q1 = wrow + g + 8;
            float2 v0 = make_float2(acc[nt][0] - hx.x, acc[nt][1] - hx.y);
            float2 v1 = make_float2(acc[nt][2] - hx.x, acc[nt][3] - hx.y);
            *(float2*)(s_sc + (2 * q0 + hc) * 36 + sl) = v0;
            *(float2*)(s_sc + (2 * q1 + hc) * 36 + sl) = v1;
        }
        __syncthreads();   // (2) scores staged; MMA done reading A/B

        // shared per-query threshold (benign-stale)
        float thr = fmaxf(s_minv[thrb], s_minv[thrb + 1]);

        float4 sc4[8];
#pragma unroll
        for (int q = 0; q < 8; ++q) sc4[q] = *(const float4*)(s_sc + sbase + q * 4);
        float tmax = -INFINITY;
#pragma unroll
        for (int q = 0; q < 8; ++q)
            tmax = fmaxf(tmax, fmaxf(fmaxf(sc4[q].x, sc4[q].y), fmaxf(sc4[q].z, sc4[q].w)));
        float thr_eff = fmaxf(thr, vals[KNN - 1]);

        if (tmax > thr_eff) {
            int mbase = m0 + mhalf;
            const float* scr = (const float*)sc4;
#pragma unroll
            for (int j = 0; j < 32; ++j) {
                float sc = scr[j];
                if (sc > vals[KNN - 1] && sc > thr) {
                    vals[KNN - 1] = sc; idxs[KNN - 1] = mbase + j;
#pragma unroll
                    for (int qq = KNN - 1; qq > 0; --qq) {
                        bool sw = vals[qq] > vals[qq - 1];
                        float tv = sw ? vals[qq - 1] : vals[qq];
                        float tu = sw ? vals[qq]     : vals[qq - 1];
                        int   ta = sw ? idxs[qq - 1] : idxs[qq];
                        int   tb = sw ? idxs[qq]     : idxs[qq - 1];
                        vals[qq] = tv; vals[qq - 1] = tu;
                        idxs[qq] = ta; idxs[qq - 1] = tb;
                    }
                }
            }
            s_minv[t] = vals[KNN - 1];
        }
        // no sync here: next B-load writes OFF_B/hxx only (disjoint from s_sc/s_minv reads)
    }
    __syncthreads();

    // dump per-owner sorted lists (alias A/B region)
#pragma unroll
    for (int j = 0; j < KNN; ++j) {
        s_mv[t * KNN + j] = vals[j];
        s_mi[t * KNN + j] = idxs[j];
    }
    __syncthreads();

    // 2-way merge per query (owners 2q, 2q+1)
    if (t < QT) {
        int ha = 0, hb = 0;
        int oa = (2 * t) * KNN, ob = (2 * t + 1) * KNN;
        int obase = (b * Nn + n0 + t) * KNN;
        for (int kk = 0; kk < KNN; ++kk) {
            float va = (ha < KNN) ? s_mv[oa + ha] : -INFINITY;
            float vb = (hb < KNN) ? s_mv[ob + hb] : -INFINITY;
            int   ia = (ha < KNN) ? s_mi[oa + ha] : 0x7fffffff;
            int   ib = (hb < KNN) ? s_mi[ob + hb] : 0x7fffffff;
            bool takeA = (va > vb) || (va == vb && ia < ib);
            g_idx[obase + kk] = takeA ? ia : ib;
            if (takeA) ++ha; else ++hb;
        }
    }
}

// ---------------- K3: projections ----------------
__global__ void proj_kernel(const float* __restrict__ x, const float* __restrict__ W) {
    __shared__ float s_w1[Cn][On];
    __shared__ float s_wd[Cn][On];
    __shared__ float s_x[Cn][32];

    int t = threadIdx.x;
    for (int i = t; i < On * Cn; i += 256) {
        int o = i / Cn, c = i % Cn;
        float w1 = W[o * (2 * Cn) + c];
        float w2 = W[o * (2 * Cn) + Cn + c];
        s_w1[c][o] = w1;
        s_wd[c][o] = w2 - w1;
    }
    int b  = blockIdx.x / (Nn / 32);
    int n0 = (blockIdx.x % (Nn / 32)) * 32;
    for (int i = t; i < Cn * 32; i += 256) {
        int c = i / 32, p = i % 32;
        s_x[c][p] = x[b * Cn * Nn + c * Nn + n0 + p];
    }
    __syncthreads();

    int warp = t >> 5, lane = t & 31;
    int p0 = warp * 4;
    float au0[4] = {0,0,0,0}, au1[4] = {0,0,0,0};
    float av0[4] = {0,0,0,0}, av1[4] = {0,0,0,0};

#pragma unroll 8
    for (int c = 0; c < Cn; ++c) {
        float w1l = s_w1[c][lane], w1h = s_w1[c][lane + 32];
        float wdl = s_wd[c][lane], wdh = s_wd[c][lane + 32];
#pragma unroll
        for (int pp = 0; pp < 4; ++pp) {
            float xv = s_x[c][p0 + pp];
            au0[pp] = fmaf(xv, w1l, au0[pp]);
            au1[pp] = fmaf(xv, w1h, au1[pp]);
            av0[pp] = fmaf(xv, wdl, av0[pp]);
            av1[pp] = fmaf(xv, wdh, av1[pp]);
        }
    }
#pragma unroll
    for (int pp = 0; pp < 4; ++pp) {
        int pt = b * Nn + n0 + p0 + pp;
        g_u[pt * On + lane]      = au0[pp];
        g_u[pt * On + 32 + lane] = au1[pp];
        g_v[pt * On + lane]      = av0[pp];
        g_v[pt * On + 32 + lane] = av1[pp];
    }
}

// ---------------- K0: zero stats ----------------
__global__ void zero_kernel() {
    int t = threadIdx.x;
    if (t < On) { g_sum[t] = 0.f; g_sumsq[t] = 0.f; }
}

// ---------------- K4: gather, max/min over k, stats ----------------
__global__ void maxstats_kernel(const float* __restrict__ gamma) {
    __shared__ float ssum[8][On];
    __shared__ float ssq[8][On];
    int warp = threadIdx.x >> 5, lane = threadIdx.x & 31;
    int pt = blockIdx.x * 8 + warp;
    int b = pt >> 12;

    const float* vp = g_v + pt * On;
    float v0 = vp[lane], v1 = vp[lane + 32];
    float mx0 = -INFINITY, mx1 = -INFINITY, mn0 = INFINITY, mn1 = INFINITY;
    float s0 = 0.f, s1 = 0.f, q0 = 0.f, q1 = 0.f;
    const int* ip = g_idx + pt * KNN;

#pragma unroll
    for (int k = 0; k < KNN; ++k) {
        int m = ip[k];
        const float* up = g_u + ((b << 12) + m) * On;
        float y0 = up[lane] + v0;
        float y1 = up[lane + 32] + v1;
        mx0 = fmaxf(mx0, y0); mn0 = fminf(mn0, y0);
        mx1 = fmaxf(mx1, y1); mn1 = fminf(mn1, y1);
        s0 += y0; q0 = fmaf(y0, y0, q0);
        s1 += y1; q1 = fmaf(y1, y1, q1);
    }
    float g0 = gamma[lane], g1 = gamma[lane + 32];
    g_sel[pt * On + lane]      = (g0 >= 0.f) ? mx0 : mn0;
    g_sel[pt * On + 32 + lane] = (g1 >= 0.f) ? mx1 : mn1;

    ssum[warp][lane] = s0; ssum[warp][lane + 32] = s1;
    ssq[warp][lane]  = q0; ssq[warp][lane + 32]  = q1;
    __syncthreads();
    if (threadIdx.x < On) {
        float ts = 0.f, tq = 0.f;
#pragma unroll
        for (int w = 0; w < 8; ++w) { ts += ssum[w][threadIdx.x]; tq += ssq[w][threadIdx.x]; }
        atomicAdd(&g_sum[threadIdx.x], ts);
        atomicAdd(&g_sumsq[threadIdx.x], tq);
    }
}

// ---------------- K6: BN coefficients ----------------
__global__ void bnfinal_kernel(const float* __restrict__ gamma, const float* __restrict__ beta) {
    int o = threadIdx.x;
    if (o < On) {
        const float M = (float)(Bn * Nn * KNN);
        float mean = g_sum[o] / M;
        float var  = g_sumsq[o] / M - mean * mean;
        var = fmaxf(var, 0.f);
        float a = gamma[o] * rsqrtf(var + EPSC);
        g_cA[o] = a;
        g_cB[o] = beta[o] - mean * a;
    }
}

// ---------------- K7: finalize + transpose ----------------
__global__ void finalize_kernel(float* __restrict__ out) {
    __shared__ float tile[32][On + 1];
    __shared__ float sA[On], sB[On];
    int t = threadIdx.x;
    int b  = blockIdx.x / (Nn / 32);
    int n0 = (blockIdx.x % (Nn / 32)) * 32;
    if (t < On) { sA[t] = g_cA[t]; sB[t] = g_cB[t]; }
    for (int i = t; i < 32 * On; i += 256) {
        int nl = i / On, o = i % On;
        tile[nl][o] = g_sel[(b * Nn + n0) * On + i];
    }
    __syncthreads();
    for (int i = t; i < 32 * On; i += 256) {
        int o = i / 32, nl = i % 32;
        float y = tile[nl][o];
        float val = fmaf(sA[o], y, sB[o]);
        out[b * On * Nn + o * Nn + n0 + nl] = (val >= 0.f) ? val : SLOPE * val;
    }
}

// ---------------- launch ----------------
// knn at position 4 (harness ncu -s 5 -c 1 lands there).
extern "C" void kernel_launch(void* const* d_in, const int* in_sizes, int n_in,
                              void* d_out, int out_size) {
    const float* x     = (const float*)d_in[0];
    const float* W     = (const float*)d_in[1];
    const float* gamma = (const float*)d_in[2];
    const float* beta  = (const float*)d_in[3];
    float* out = (float*)d_out;

    cudaFuncSetAttribute(knn_kernel, cudaFuncAttributeMaxDynamicSharedMemorySize, SMEM_KNN);

    xx_kernel<<<(Bn * Nn) / 256, 256>>>(x);
    split_kernel<<<Bn * (Nn / 64), 256>>>(x);
    proj_kernel<<<Bn * (Nn / 32), 256>>>(x, W);
    knn_kernel<<<Bn * (Nn / QT), 256, SMEM_KNN>>>();
    zero_kernel<<<1, 64>>>();
    maxstats_kernel<<<(Bn * Nn) / 8, 256>>>(gamma);
    bnfinal_kernel<<<1, 64>>>(gamma, beta);
    finalize_kernel<<<Bn * (Nn / 32), 256>>>(out);
}

// round 13
// speedup vs baseline: 1.4438x; 1.4438x over previous
#include <cuda_runtime.h>
#include <cuda_bf16.h>
#include <math.h>
#include <stdint.h>

#define Bn   8
#define Cn   64
#define Nn   4096
#define On   64
#define KNN  20
#define SLOPE 0.2f
#define EPSC  1e-5f

// warp-level bf16 MMA (sm_80+, baseline sm_103-safe; tcgen05 is NOT available here)
#define MMA_BF16(c, a, b0, b1) \
    asm volatile("mma.sync.aligned.m16n8k16.row.col.f32.bf16.bf16.f32 " \
        "{%0,%1,%2,%3}, {%4,%5,%6,%7}, {%8,%9}, {%0,%1,%2,%3};" \
        : "+f"((c)[0]), "+f"((c)[1]), "+f"((c)[2]), "+f"((c)[3]) \
        : "r"((a)[0]), "r"((a)[1]), "r"((a)[2]), "r"((a)[3]), "r"(b0), "r"(b1))

#define LDM_X4(r, addr) \
    asm volatile("ldmatrix.sync.aligned.m8n8.x4.shared.b16 {%0,%1,%2,%3}, [%4];" \
        : "=r"((r)[0]), "=r"((r)[1]), "=r"((r)[2]), "=r"((r)[3]) : "r"(addr))

__device__ __forceinline__ uint32_t smem_u32(const void* p) {
    uint32_t a;
    asm("{ .reg .u64 t; cvta.to.shared.u64 t, %1; cvt.u32.u64 %0, t; }" : "=r"(a) : "l"(p));
    return a;
}

// ---------------- device scratch ----------------
__device__ float g_xx[Bn * Nn];
__device__ int   g_idx[Bn * Nn * KNN];
__device__ float g_u[Bn * Nn * On];
__device__ float g_v[Bn * Nn * On];
__device__ float g_sel[Bn * Nn * On];
__device__ float g_sum[On];
__device__ float g_sumsq[On];
__device__ float g_cA[On];
__device__ float g_cB[On];
__device__ __nv_bfloat16 g_s[Bn * Nn * 192];   // [b][n][b0|b1|b2] bf16 splits

// ---------------- K1: squared norms ----------------
__global__ void xx_kernel(const float* __restrict__ x) {
    int i = blockIdx.x * 256 + threadIdx.x;
    int b = i >> 12;
    int n = i & (Nn - 1);
    const float* xp = x + b * Cn * Nn + n;
    float s = 0.f;
#pragma unroll
    for (int c = 0; c < Cn; ++c) { float v = xp[c * Nn]; s = fmaf(v, v, s); }
    g_xx[i] = s;
}

// ---------------- K1b: bf16x3 split + transpose ----------------
__global__ void split_kernel(const float* __restrict__ x) {
    __shared__ alignas(16) __nv_bfloat16 sb0[64 * 72];
    __shared__ alignas(16) __nv_bfloat16 sb1[64 * 72];
    __shared__ alignas(16) __nv_bfloat16 sb2[64 * 72];

    int t = threadIdx.x;
    int b = blockIdx.x >> 6;
    int n0 = (blockIdx.x & 63) * 64;

#pragma unroll
    for (int j = 0; j < 16; ++j) {
        int idx = j * 256 + t;
        int c = idx >> 6, n = idx & 63;
        float v = x[b * Cn * Nn + c * Nn + n0 + n];
        __nv_bfloat16 h0 = __float2bfloat16(v);
        float f0 = __bfloat162float(h0);
        __nv_bfloat16 h1 = __float2bfloat16(v - f0);
        float f1 = __bfloat162float(h1);
        __nv_bfloat16 h2 = __float2bfloat16(v - f0 - f1);
        sb0[n * 72 + c] = h0;
        sb1[n * 72 + c] = h1;
        sb2[n * 72 + c] = h2;
    }
    __syncthreads();

    uint4* g4 = (uint4*)g_s;
#pragma unroll
    for (int j = 0; j < 6; ++j) {
        int idx = j * 256 + t;
        int r = idx / 24, u = idx % 24;
        int ch = u >> 3, c8 = (u & 7) * 8;
        const __nv_bfloat16* src = (ch == 0) ? sb0 : (ch == 1) ? sb1 : sb2;
        g4[(b * Nn + n0 + r) * 24 + u] = *(const uint4*)(src + r * 72 + c8);
    }
}

// ---------------- K2: mma.sync + ldmatrix + warp-local top-K ----------------
// CTA: 64 queries, 8 warps. Warp (w&3): rows (w&3)*16; w>=4: cols 32..63.
// Double-buffered B; one __syncthreads per tile. Owners are warp-local:
// lane o owns (row wrow+(o>>1), 16-col subset (o&1)); staging 8 STS.64 +
// __syncwarp + 4 LDS.128 (conflict-free, stride 20 words).
#define QT 64
#define CT 64
#define SROW 400

#define OFF_A    0                     // 25600
#define OFF_B    25600                 // 2 x 25600 -> 76800
#define OFF_HXX  76800                 // 2 x 64 f  -> 77312
#define OFF_STG  77312                 // 8 warps x 32 owners x 20 f = 20480 -> 97792
#define OFF_MINV 97792                 // 64 rows x 4 subs f = 1024 -> 98816
#define SMEM_KNN 98816
#define OFF_MV   0                     // post-loop alias (A region): 64*4*20*4 = 20480
#define OFF_MI   25600                 // post-loop alias (B region): 20480

__global__ void __launch_bounds__(256, 2) knn_kernel() {
    extern __shared__ char sm[];
    uint32_t smb = smem_u32(sm);
    float* s_hxx  = (float*)(sm + OFF_HXX);
    float* s_minv = (float*)(sm + OFF_MINV);
    float* s_mv   = (float*)(sm + OFF_MV);
    int*   s_mi   = (int*)  (sm + OFF_MI);

    int t = threadIdx.x, w = t >> 5, lane = t & 31;
    int g = lane >> 2, q4 = lane & 3;
    int b = blockIdx.x >> 6;
    int n0 = (blockIdx.x & 63) * QT;

    int wrow = (w & 3) * 16;
    int ntb  = (w >= 4) ? 4 : 0;       // n-tile base (cols ntb*8)

    const uint4* gs4 = (const uint4*)g_s;
    // resident A: 64 rows x 24 uint4
#pragma unroll
    for (int j = 0; j < 6; ++j) {
        int idx = j * 256 + t;
        int r = idx / 24, u = idx % 24;
        *(uint4*)(sm + OFF_A + r * SROW + u * 16) = gs4[(b * Nn + n0 + r) * 24 + u];
    }
    // B tile 0 + hxx 0
#pragma unroll
    for (int j = 0; j < 6; ++j) {
        int idx = j * 256 + t;
        int r = idx / 24, u = idx % 24;
        *(uint4*)(sm + OFF_B + r * SROW + u * 16) = gs4[(b * Nn + r) * 24 + u];
    }
    if (t < CT) s_hxx[t] = 0.5f * g_xx[b * Nn + t];
    for (int i = t; i < 256; i += 256) s_minv[i] = -INFINITY;
    __syncthreads();

    // ldmatrix per-lane source addresses
    uint32_t aaddr = smb + OFF_A
        + (uint32_t)((wrow + ((lane >> 3) & 1) * 8 + (lane & 7)) * SROW)
        + (uint32_t)((lane >> 4) * 16);
    uint32_t brow = (uint32_t)(ntb * 8 + (lane >> 4) * 8 + (lane & 7));
    uint32_t bk   = (uint32_t)(((lane >> 3) & 1) * 16);
    uint32_t baddr0 = smb + OFF_B + brow * SROW + bk;           // buf 0
    uint32_t baddr1 = baddr0 + 25600;                           // buf 1

    float* stg = (float*)(sm + OFF_STG) + w * 640;              // 32 owners x 20
    int og0 = (g * 2 + (q4 >> 1)) * 20;
    int og1 = ((g + 8) * 2 + (q4 >> 1)) * 20;
    int slot0 = (q4 & 1) * 2;
    int rbase = (wrow + (lane >> 1)) * 4;
    int mvslot = rbase + (ntb ? 2 : 0) + (lane & 1);
    int hxb = ntb * 8 + 2 * q4;

    float vals[KNN];
    int   idxs[KNN];
#pragma unroll
    for (int j = 0; j < KNN; ++j) { vals[j] = -INFINITY; idxs[j] = 0x7fffffff; }

    for (int ti = 0; ti < Nn / CT; ++ti) {
        int buf = ti & 1;
        // prefetch next B tile + hxx into other buffer
        if (ti < Nn / CT - 1) {
            int m0n = (ti + 1) * CT;
            char* dst = sm + OFF_B + (buf ^ 1) * 25600;
#pragma unroll
            for (int j = 0; j < 6; ++j) {
                int idx = j * 256 + t;
                int r = idx / 24, u = idx % 24;
                *(uint4*)(dst + r * SROW + u * 16) = gs4[(b * Nn + m0n + r) * 24 + u];
            }
            if (t < CT) s_hxx[(buf ^ 1) * 64 + t] = 0.5f * g_xx[b * Nn + m0n + t];
        }

        // ---- MMA on current buffer ----
        uint32_t ba = buf ? baddr1 : baddr0;
        float acc[4][4];
#pragma unroll
        for (int nt = 0; nt < 4; ++nt)
#pragma unroll
            for (int e = 0; e < 4; ++e) acc[nt][e] = 0.f;

#pragma unroll
        for (int ks = 0; ks < 4; ++ks) {
            uint32_t a0[4], a1[4], a2[4];
            uint32_t ak = aaddr + ks * 32;
            LDM_X4(a0, ak);
            LDM_X4(a1, ak + 128);
            LDM_X4(a2, ak + 256);
#pragma unroll
            for (int p = 0; p < 2; ++p) {
                uint32_t b0[4], b1[4], b2[4];
                uint32_t bb = ba + (uint32_t)(p * 16 * SROW) + ks * 32;
                LDM_X4(b0, bb);
                LDM_X4(b1, bb + 128);
                LDM_X4(b2, bb + 256);
                float* cA = acc[2 * p];
                float* cB = acc[2 * p + 1];
                MMA_BF16(cA, a0, b0[0], b0[1]);  MMA_BF16(cB, a0, b0[2], b0[3]);
                MMA_BF16(cA, a1, b1[0], b1[1]);  MMA_BF16(cB, a1, b1[2], b1[3]);
                MMA_BF16(cA, a0, b1[0], b1[1]);  MMA_BF16(cB, a0, b1[2], b1[3]);
                MMA_BF16(cA, a1, b0[0], b0[1]);  MMA_BF16(cB, a1, b0[2], b0[3]);
                MMA_BF16(cA, a0, b2[0], b2[1]);  MMA_BF16(cB, a0, b2[2], b2[3]);
                MMA_BF16(cA, a2, b0[0], b0[1]);  MMA_BF16(cB, a2, b0[2], b0[3]);
            }
        }

        // ---- stage (writer-side score = I - 0.5*xx), warp-local ----
        int m0 = ti * CT;
#pragma unroll
        for (int nt = 0; nt < 4; ++nt) {
            float2 hx = *(const float2*)(s_hxx + buf * 64 + hxb + nt * 8);
            *(float2*)(stg + og0 + nt * 4 + slot0) =
                make_float2(acc[nt][0] - hx.x, acc[nt][1] - hx.y);
            *(float2*)(stg + og1 + nt * 4 + slot0) =
                make_float2(acc[nt][2] - hx.x, acc[nt][3] - hx.y);
        }
        __syncwarp();

        // ---- owner scan: lane o = (row<<1)|colsub ----
        const float4* sp = (const float4*)(stg + lane * 20);
        float4 v0 = sp[0], v1 = sp[1], v2 = sp[2], v3 = sp[3];
        float tmax = fmaxf(
            fmaxf(fmaxf(fmaxf(v0.x, v0.y), fmaxf(v0.z, v0.w)),
                  fmaxf(fmaxf(v1.x, v1.y), fmaxf(v1.z, v1.w))),
            fmaxf(fmaxf(fmaxf(v2.x, v2.y), fmaxf(v2.z, v2.w)),
                  fmaxf(fmaxf(v3.x, v3.y), fmaxf(v3.z, v3.w))));
        float thr = fmaxf(fmaxf(s_minv[rbase], s_minv[rbase + 1]),
                          fmaxf(s_minv[rbase + 2], s_minv[rbase + 3]));
        if (tmax > fmaxf(thr, vals[KNN - 1])) {
            float sc[16];
            sc[0]=v0.x; sc[1]=v0.y; sc[2]=v0.z; sc[3]=v0.w;
            sc[4]=v1.x; sc[5]=v1.y; sc[6]=v1.z; sc[7]=v1.w;
            sc[8]=v2.x; sc[9]=v2.y; sc[10]=v2.z; sc[11]=v2.w;
            sc[12]=v3.x; sc[13]=v3.y; sc[14]=v3.z; sc[15]=v3.w;
            int mbase = m0 + ntb * 8 + 4 * (lane & 1);
#pragma unroll
            for (int j = 0; j < 16; ++j) {
                float v = sc[j];
                if (v > vals[KNN - 1] && v > thr) {
                    vals[KNN - 1] = v;
                    idxs[KNN - 1] = mbase + ((j >> 2) << 3) + (j & 3);
#pragma unroll
                    for (int q = KNN - 1; q > 0; --q) {
                        bool sw = vals[q] > vals[q - 1];
                        float tv = sw ? vals[q - 1] : vals[q];
                        float tu = sw ? vals[q]     : vals[q - 1];
                        int   ta = sw ? idxs[q - 1] : idxs[q];
                        int   tb = sw ? idxs[q]     : idxs[q - 1];
                        vals[q] = tv; vals[q - 1] = tu;
                        idxs[q] = ta; idxs[q - 1] = tb;
                    }
                }
            }
            s_minv[mvslot] = vals[KNN - 1];
        }
        __syncthreads();   // B-buf + staging reuse barrier
    }

    // ---- dump lists, 4-way merge per row ----
    int owner_id = rbase + (ntb ? 2 : 0) + (lane & 1);   // row*4 + sub
#pragma unroll
    for (int j = 0; j < KNN; ++j) {
        s_mv[owner_id * KNN + j] = vals[j];
        s_mi[owner_id * KNN + j] = idxs[j];
    }
    __syncthreads();

    if (t < QT) {
        int head[4] = {0, 0, 0, 0};
        int lb = t * 4;
        int obase = (b * Nn + n0 + t) * KNN;
        for (int kk = 0; kk < KNN; ++kk) {
            float bv = -INFINITY; int bi = 0x7fffffff; int bs = 0;
#pragma unroll
            for (int s = 0; s < 4; ++s) {
                int h = head[s];
                if (h < KNN) {
                    float v  = s_mv[(lb + s) * KNN + h];
                    int   im = s_mi[(lb + s) * KNN + h];
                    if (v > bv || (v == bv && im < bi)) { bv = v; bi = im; bs = s; }
                }
            }
            g_idx[obase + kk] = bi;
            head[bs]++;
        }
    }
}

// ---------------- K3: projections ----------------
__global__ void proj_kernel(const float* __restrict__ x, const float* __restrict__ W) {
    __shared__ float s_w1[Cn][On];
    __shared__ float s_wd[Cn][On];
    __shared__ float s_x[Cn][32];

    int t = threadIdx.x;
    for (int i = t; i < On * Cn; i += 256) {
        int o = i / Cn, c = i % Cn;
        float w1 = W[o * (2 * Cn) + c];
        float w2 = W[o * (2 * Cn) + Cn + c];
        s_w1[c][o] = w1;
        s_wd[c][o] = w2 - w1;
    }
    int b  = blockIdx.x / (Nn / 32);
    int n0 = (blockIdx.x % (Nn / 32)) * 32;
    for (int i = t; i < Cn * 32; i += 256) {
        int c = i / 32, p = i % 32;
        s_x[c][p] = x[b * Cn * Nn + c * Nn + n0 + p];
    }
    __syncthreads();

    int warp = t >> 5, lane = t & 31;
    int p0 = warp * 4;
    float au0[4] = {0,0,0,0}, au1[4] = {0,0,0,0};
    float av0[4] = {0,0,0,0}, av1[4] = {0,0,0,0};

#pragma unroll 8
    for (int c = 0; c < Cn; ++c) {
        float w1l = s_w1[c][lane], w1h = s_w1[c][lane + 32];
        float wdl = s_wd[c][lane], wdh = s_wd[c][lane + 32];
#pragma unroll
        for (int pp = 0; pp < 4; ++pp) {
            float xv = s_x[c][p0 + pp];
            au0[pp] = fmaf(xv, w1l, au0[pp]);
            au1[pp] = fmaf(xv, w1h, au1[pp]);
            av0[pp] = fmaf(xv, wdl, av0[pp]);
            av1[pp] = fmaf(xv, wdh, av1[pp]);
        }
    }
#pragma unroll
    for (int pp = 0; pp < 4; ++pp) {
        int pt = b * Nn + n0 + p0 + pp;
        g_u[pt * On + lane]      = au0[pp];
        g_u[pt * On + 32 + lane] = au1[pp];
        g_v[pt * On + lane]      = av0[pp];
        g_v[pt * On + 32 + lane] = av1[pp];
    }
}

// ---------------- K0: zero stats ----------------
__global__ void zero_kernel() {
    int t = threadIdx.x;
    if (t < On) { g_sum[t] = 0.f; g_sumsq[t] = 0.f; }
}

// ---------------- K4: gather, max/min over k, stats ----------------
__global__ void maxstats_kernel(const float* __restrict__ gamma) {
    __shared__ float ssum[8][On];
    __shared__ float ssq[8][On];
    int warp = threadIdx.x >> 5, lane = threadIdx.x & 31;
    int pt = blockIdx.x * 8 + warp;
    int b = pt >> 12;

    const float* vp = g_v + pt * On;
    float v0 = vp[lane], v1 = vp[lane + 32];
    float mx0 = -INFINITY, mx1 = -INFINITY, mn0 = INFINITY, mn1 = INFINITY;
    float s0 = 0.f, s1 = 0.f, q0 = 0.f, q1 = 0.f;
    const int* ip = g_idx + pt * KNN;

#pragma unroll
    for (int k = 0; k < KNN; ++k) {
        int m = ip[k];
        const float* up = g_u + ((b << 12) + m) * On;
        float y0 = up[lane] + v0;
        float y1 = up[lane + 32] + v1;
        mx0 = fmaxf(mx0, y0); mn0 = fminf(mn0, y0);
        mx1 = fmaxf(mx1, y1); mn1 = fminf(mn1, y1);
        s0 += y0; q0 = fmaf(y0, y0, q0);
        s1 += y1; q1 = fmaf(y1, y1, q1);
    }
    float g0 = gamma[lane], g1 = gamma[lane + 32];
    g_sel[pt * On + lane]      = (g0 >= 0.f) ? mx0 : mn0;
    g_sel[pt * On + 32 + lane] = (g1 >= 0.f) ? mx1 : mn1;

    ssum[warp][lane] = s0; ssum[warp][lane + 32] = s1;
    ssq[warp][lane]  = q0; ssq[warp][lane + 32]  = q1;
    __syncthreads();
    if (threadIdx.x < On) {
        float ts = 0.f, tq = 0.f;
#pragma unroll
        for (int w = 0; w < 8; ++w) { ts += ssum[w][threadIdx.x]; tq += ssq[w][threadIdx.x]; }
        atomicAdd(&g_sum[threadIdx.x], ts);
        atomicAdd(&g_sumsq[threadIdx.x], tq);
    }
}

// ---------------- K6: BN coefficients ----------------
__global__ void bnfinal_kernel(const float* __restrict__ gamma, const float* __restrict__ beta) {
    int o = threadIdx.x;
    if (o < On) {
        const float M = (float)(Bn * Nn * KNN);
        float mean = g_sum[o] / M;
        float var  = g_sumsq[o] / M - mean * mean;
        var = fmaxf(var, 0.f);
        float a = gamma[o] * rsqrtf(var + EPSC);
        g_cA[o] = a;
        g_cB[o] = beta[o] - mean * a;
    }
}

// ---------------- K7: finalize + transpose ----------------
__global__ void finalize_kernel(float* __restrict__ out) {
    __shared__ float tile[32][On + 1];
    __shared__ float sA[On], sB[On];
    int t = threadIdx.x;
    int b  = blockIdx.x / (Nn / 32);
    int n0 = (blockIdx.x % (Nn / 32)) * 32;
    if (t < On) { sA[t] = g_cA[t]; sB[t] = g_cB[t]; }
    for (int i = t; i < 32 * On; i += 256) {
        int nl = i / On, o = i % On;
        tile[nl][o] = g_sel[(b * Nn + n0) * On + i];
    }
    __syncthreads();
    for (int i = t; i < 32 * On; i += 256) {
        int o = i / 32, nl = i % 32;
        float y = tile[nl][o];
        float val = fmaf(sA[o], y, sB[o]);
        out[b * On * Nn + o * Nn + n0 + nl] = (val >= 0.f) ? val : SLOPE * val;
    }
}

// ---------------- launch ----------------
// knn at position 4 (harness ncu -s 5 -c 1 lands there).
extern "C" void kernel_launch(void* const* d_in, const int* in_sizes, int n_in,
                              void* d_out, int out_size) {
    const float* x     = (const float*)d_in[0];
    const float* W     = (const float*)d_in[1];
    const float* gamma = (const float*)d_in[2];
    const float* beta  = (const float*)d_in[3];
    float* out = (float*)d_out;

    cudaFuncSetAttribute(knn_kernel, cudaFuncAttributeMaxDynamicSharedMemorySize, SMEM_KNN);

    xx_kernel<<<(Bn * Nn) / 256, 256>>>(x);
    split_kernel<<<Bn * (Nn / 64), 256>>>(x);
    proj_kernel<<<Bn * (Nn / 32), 256>>>(x, W);
    knn_kernel<<<Bn * (Nn / QT), 256, SMEM_KNN>>>();
    zero_kernel<<<1, 64>>>();
    maxstats_kernel<<<(Bn * Nn) / 8, 256>>>(gamma);
    bnfinal_kernel<<<1, 64>>>(gamma, beta);
    finalize_kernel<<<Bn * (Nn / 32), 256>>>(out);
}

// round 14
// speedup vs baseline: 1.8494x; 1.2810x over previous
#include <cuda_runtime.h>
#include <cuda_bf16.h>
#include <math.h>
#include <stdint.h>

#define Bn   8
#define Cn   64
#define Nn   4096
#define On   64
#define KNN  20
#define SLOPE 0.2f
#define EPSC  1e-5f

// warp-level bf16 MMA (sm_80+, baseline sm_103-safe; tcgen05 is NOT available here)
#define MMA_BF16(c, a, b0, b1) \
    asm volatile("mma.sync.aligned.m16n8k16.row.col.f32.bf16.bf16.f32 " \
        "{%0,%1,%2,%3}, {%4,%5,%6,%7}, {%8,%9}, {%0,%1,%2,%3};" \
        : "+f"((c)[0]), "+f"((c)[1]), "+f"((c)[2]), "+f"((c)[3]) \
        : "r"((a)[0]), "r"((a)[1]), "r"((a)[2]), "r"((a)[3]), "r"(b0), "r"(b1))

#define LDM_X4(r, addr) \
    asm volatile("ldmatrix.sync.aligned.m8n8.x4.shared.b16 {%0,%1,%2,%3}, [%4];" \
        : "=r"((r)[0]), "=r"((r)[1]), "=r"((r)[2]), "=r"((r)[3]) : "r"(addr))

__device__ __forceinline__ uint32_t smem_u32(const void* p) {
    uint32_t a;
    asm("{ .reg .u64 t; cvta.to.shared.u64 t, %1; cvt.u32.u64 %0, t; }" : "=r"(a) : "l"(p));
    return a;
}

// ---------------- device scratch ----------------
__device__ float g_xx[Bn * Nn];
__device__ int   g_idx[Bn * Nn * KNN];
__device__ float g_u[Bn * Nn * On];
__device__ float g_v[Bn * Nn * On];
__device__ float g_sel[Bn * Nn * On];
__device__ float g_sum[On];
__device__ float g_sumsq[On];
__device__ float g_cA[On];
__device__ float g_cB[On];
__device__ __nv_bfloat16 g_s[Bn * Nn * 192];   // [b][n][b0|b1|b2] bf16 splits

// ---------------- K1: squared norms ----------------
__global__ void xx_kernel(const float* __restrict__ x) {
    int i = blockIdx.x * 256 + threadIdx.x;
    int b = i >> 12;
    int n = i & (Nn - 1);
    const float* xp = x + b * Cn * Nn + n;
    float s = 0.f;
#pragma unroll
    for (int c = 0; c < Cn; ++c) { float v = xp[c * Nn]; s = fmaf(v, v, s); }
    g_xx[i] = s;
}

// ---------------- K1b: bf16x3 split + transpose ----------------
__global__ void split_kernel(const float* __restrict__ x) {
    __shared__ alignas(16) __nv_bfloat16 sb0[64 * 72];
    __shared__ alignas(16) __nv_bfloat16 sb1[64 * 72];
    __shared__ alignas(16) __nv_bfloat16 sb2[64 * 72];

    int t = threadIdx.x;
    int b = blockIdx.x >> 6;
    int n0 = (blockIdx.x & 63) * 64;

#pragma unroll
    for (int j = 0; j < 16; ++j) {
        int idx = j * 256 + t;
        int c = idx >> 6, n = idx & 63;
        float v = x[b * Cn * Nn + c * Nn + n0 + n];
        __nv_bfloat16 h0 = __float2bfloat16(v);
        float f0 = __bfloat162float(h0);
        __nv_bfloat16 h1 = __float2bfloat16(v - f0);
        float f1 = __bfloat162float(h1);
        __nv_bfloat16 h2 = __float2bfloat16(v - f0 - f1);
        sb0[n * 72 + c] = h0;
        sb1[n * 72 + c] = h1;
        sb2[n * 72 + c] = h2;
    }
    __syncthreads();

    uint4* g4 = (uint4*)g_s;
#pragma unroll
    for (int j = 0; j < 6; ++j) {
        int idx = j * 256 + t;
        int r = idx / 24, u = idx % 24;
        int ch = u >> 3, c8 = (u & 7) * 8;
        const __nv_bfloat16* src = (ch == 0) ? sb0 : (ch == 1) ? sb1 : sb2;
        g4[(b * Nn + n0 + r) * 24 + u] = *(const uint4*)(src + r * 72 + c8);
    }
}

// ---------------- K2: mma.sync + ldmatrix + gated top-K ----------------
// CTA: 64 queries, 8 warps. Warp (w&3): rows (w&3)*16; w>=4: cols 32..63.
// Loader: thread t -> row t>>2, uint4 cols (t&3)+4j  (no div/mod, 1 pointer).
// Insert: qualify-mask + __ffs loop so the 120-instr sorted shift executes
// only for qualifying candidates (R13 paid it predicated per-candidate).
#define QT 64
#define CT 64
#define SROW 400

#define OFF_A    0                     // 25600
#define OFF_B    25600                 // 2 x 25600 -> 76800
#define OFF_HXX  76800                 // 2 x 64 f  -> 77312
#define OFF_STG  77312                 // 8 warps x 32 owners x 20 f = 20480 -> 97792
#define OFF_MINV 97792                 // 64 rows x 4 subs f = 1024 -> 98816
#define SMEM_KNN 98816
#define OFF_MV   0                     // post-loop alias (A region)
#define OFF_MI   25600                 // post-loop alias (B region)

__global__ void __launch_bounds__(256, 2) knn_kernel() {
    extern __shared__ char sm[];
    uint32_t smb = smem_u32(sm);
    float* s_hxx  = (float*)(sm + OFF_HXX);
    float* s_minv = (float*)(sm + OFF_MINV);
    float* s_mv   = (float*)(sm + OFF_MV);
    int*   s_mi   = (int*)  (sm + OFF_MI);

    int t = threadIdx.x, w = t >> 5, lane = t & 31;
    int g = lane >> 2, q4 = lane & 3;
    int b = blockIdx.x >> 6;
    int n0 = (blockIdx.x & 63) * QT;

    int wrow = (w & 3) * 16;
    int ntb  = (w >= 4) ? 4 : 0;       // n-tile base (cols ntb*8)

    const uint4* gs4 = (const uint4*)g_s;
    // loader mapping: row lr = t>>2, uint4 col lu = (t&3) + 4*j
    int lr = t >> 2, lu = t & 3;
    const uint4* gA = gs4 + (size_t)(b * Nn + n0 + lr) * 24 + lu;
    const uint4* gB = gs4 + (size_t)(b * Nn + lr) * 24 + lu;
    uint32_t dstA = (uint32_t)(OFF_A + lr * SROW + lu * 16);
    uint32_t dstB = (uint32_t)(OFF_B + lr * SROW + lu * 16);
#pragma unroll
    for (int j = 0; j < 6; ++j) {
        *(uint4*)(sm + dstA + j * 64) = gA[j * 4];
        *(uint4*)(sm + dstB + j * 64) = gB[j * 4];
    }
    gB += CT * 24;                      // points at tile 1
    const float* gxxp = g_xx + b * Nn + t;
    if (t < CT) s_hxx[t] = 0.5f * gxxp[0];
    s_minv[t] = -INFINITY;
    __syncthreads();

    // ldmatrix per-lane source addresses
    uint32_t aaddr = smb + OFF_A
        + (uint32_t)((wrow + ((lane >> 3) & 1) * 8 + (lane & 7)) * SROW)
        + (uint32_t)((lane >> 4) * 16);
    uint32_t brow = (uint32_t)(ntb * 8 + (lane >> 4) * 8 + (lane & 7));
    uint32_t bk   = (uint32_t)(((lane >> 3) & 1) * 16);
    uint32_t baddr0 = smb + OFF_B + brow * SROW + bk;           // buf 0
    uint32_t baddr1 = baddr0 + 25600;                           // buf 1

    float* stg = (float*)(sm + OFF_STG) + w * 640;              // 32 owners x 20
    int og0 = (g * 2 + (q4 >> 1)) * 20;
    int og1 = ((g + 8) * 2 + (q4 >> 1)) * 20;
    int slot0 = (q4 & 1) * 2;
    int rbase = (wrow + (lane >> 1)) * 4;
    int mvslot = rbase + (ntb ? 2 : 0) + (lane & 1);
    int hxb = ntb * 8 + 2 * q4;
    const float* mystg = stg + lane * 20;

    float vals[KNN];
    int   idxs[KNN];
#pragma unroll
    for (int j = 0; j < KNN; ++j) { vals[j] = -INFINITY; idxs[j] = 0x7fffffff; }

    for (int ti = 0; ti < Nn / CT; ++ti) {
        int buf = ti & 1;
        // prefetch next B tile + hxx (no div/mod: fixed-stride pointer)
        if (ti < Nn / CT - 1) {
            uint32_t d = dstB + (uint32_t)((buf ^ 1) * 25600);
#pragma unroll
            for (int j = 0; j < 6; ++j)
                *(uint4*)(sm + d + j * 64) = gB[j * 4];
            gB += CT * 24;
            if (t < CT) s_hxx[(buf ^ 1) * 64 + t] = 0.5f * gxxp[(ti + 1) * CT];
        }

        // ---- MMA on current buffer ----
        uint32_t ba = buf ? baddr1 : baddr0;
        float acc[4][4];
#pragma unroll
        for (int nt = 0; nt < 4; ++nt)
#pragma unroll
            for (int e = 0; e < 4; ++e) acc[nt][e] = 0.f;

#pragma unroll
        for (int ks = 0; ks < 4; ++ks) {
            uint32_t a0[4], a1[4], a2[4];
            uint32_t ak = aaddr + ks * 32;
            LDM_X4(a0, ak);
            LDM_X4(a1, ak + 128);
            LDM_X4(a2, ak + 256);
#pragma unroll
            for (int p = 0; p < 2; ++p) {
                uint32_t b0[4], b1[4], b2[4];
                uint32_t bb = ba + (uint32_t)(p * 16 * SROW) + ks * 32;
                LDM_X4(b0, bb);
                LDM_X4(b1, bb + 128);
                LDM_X4(b2, bb + 256);
                float* cA = acc[2 * p];
                float* cB = acc[2 * p + 1];
                MMA_BF16(cA, a0, b0[0], b0[1]);  MMA_BF16(cB, a0, b0[2], b0[3]);
                MMA_BF16(cA, a1, b1[0], b1[1]);  MMA_BF16(cB, a1, b1[2], b1[3]);
                MMA_BF16(cA, a0, b1[0], b1[1]);  MMA_BF16(cB, a0, b1[2], b1[3]);
                MMA_BF16(cA, a1, b0[0], b0[1]);  MMA_BF16(cB, a1, b0[2], b0[3]);
                MMA_BF16(cA, a0, b2[0], b2[1]);  MMA_BF16(cB, a0, b2[2], b2[3]);
                MMA_BF16(cA, a2, b0[0], b0[1]);  MMA_BF16(cB, a2, b0[2], b0[3]);
            }
        }

        // ---- stage (score = I - 0.5*xx), warp-local ----
#pragma unroll
        for (int nt = 0; nt < 4; ++nt) {
            float2 hx = *(const float2*)(s_hxx + buf * 64 + hxb + nt * 8);
            *(float2*)(stg + og0 + nt * 4 + slot0) =
                make_float2(acc[nt][0] - hx.x, acc[nt][1] - hx.y);
            *(float2*)(stg + og1 + nt * 4 + slot0) =
                make_float2(acc[nt][2] - hx.x, acc[nt][3] - hx.y);
        }
        __syncwarp();

        // ---- owner scan: lane o = (row<<1)|colsub ----
        const float4* sp = (const float4*)mystg;
        float4 v0 = sp[0], v1 = sp[1], v2 = sp[2], v3 = sp[3];
        float tmax = fmaxf(
            fmaxf(fmaxf(fmaxf(v0.x, v0.y), fmaxf(v0.z, v0.w)),
                  fmaxf(fmaxf(v1.x, v1.y), fmaxf(v1.z, v1.w))),
            fmaxf(fmaxf(fmaxf(v2.x, v2.y), fmaxf(v2.z, v2.w)),
                  fmaxf(fmaxf(v3.x, v3.y), fmaxf(v3.z, v3.w))));
        float thr = fmaxf(fmaxf(s_minv[rbase], s_minv[rbase + 1]),
                          fmaxf(s_minv[rbase + 2], s_minv[rbase + 3]));
        float thr_eff = fmaxf(thr, vals[KNN - 1]);
        if (tmax > thr_eff) {
            // qualify mask (conservative superset vs frozen thr_eff)
            unsigned qm = 0;
            qm |= (v0.x > thr_eff) ? 0x0001u : 0u;
            qm |= (v0.y > thr_eff) ? 0x0002u : 0u;
            qm |= (v0.z > thr_eff) ? 0x0004u : 0u;
            qm |= (v0.w > thr_eff) ? 0x0008u : 0u;
            qm |= (v1.x > thr_eff) ? 0x0010u : 0u;
            qm |= (v1.y > thr_eff) ? 0x0020u : 0u;
            qm |= (v1.z > thr_eff) ? 0x0040u : 0u;
            qm |= (v1.w > thr_eff) ? 0x0080u : 0u;
            qm |= (v2.x > thr_eff) ? 0x0100u : 0u;
            qm |= (v2.y > thr_eff) ? 0x0200u : 0u;
            qm |= (v2.z > thr_eff) ? 0x0400u : 0u;
            qm |= (v2.w > thr_eff) ? 0x0800u : 0u;
            qm |= (v3.x > thr_eff) ? 0x1000u : 0u;
            qm |= (v3.y > thr_eff) ? 0x2000u : 0u;
            qm |= (v3.z > thr_eff) ? 0x4000u : 0u;
            qm |= (v3.w > thr_eff) ? 0x8000u : 0u;

            int mbase = ti * CT + ntb * 8 + 4 * (lane & 1);
            while (qm) {
                int j = __ffs(qm) - 1;
                qm &= qm - 1;
                float v = mystg[j];                 // dynamic LDS (== staged score)
                if (v > vals[KNN - 1] && v > thr) {
                    vals[KNN - 1] = v;
                    idxs[KNN - 1] = mbase + ((j >> 2) << 3) + (j & 3);
#pragma unroll
                    for (int q = KNN - 1; q > 0; --q) {
                        bool sw = vals[q] > vals[q - 1];
                        float tv = sw ? vals[q - 1] : vals[q];
                        float tu = sw ? vals[q]     : vals[q - 1];
                        int   ta = sw ? idxs[q - 1] : idxs[q];
                        int   tb = sw ? idxs[q]     : idxs[q - 1];
                        vals[q] = tv; vals[q - 1] = tu;
                        idxs[q] = ta; idxs[q - 1] = tb;
                    }
                }
            }
            s_minv[mvslot] = vals[KNN - 1];
        }
        __syncthreads();   // B-buf + staging reuse barrier
    }

    // ---- dump lists, 4-way merge per row ----
    int owner_id = rbase + (ntb ? 2 : 0) + (lane & 1);   // row*4 + sub
#pragma unroll
    for (int j = 0; j < KNN; ++j) {
        s_mv[owner_id * KNN + j] = vals[j];
        s_mi[owner_id * KNN + j] = idxs[j];
    }
    __syncthreads();

    if (t < QT) {
        int head[4] = {0, 0, 0, 0};
        int lb = t * 4;
        int obase = (b * Nn + n0 + t) * KNN;
        for (int kk = 0; kk < KNN; ++kk) {
            float bv = -INFINITY; int bi = 0x7fffffff; int bs = 0;
#pragma unroll
            for (int s = 0; s < 4; ++s) {
                int h = head[s];
                if (h < KNN) {
                    float v  = s_mv[(lb + s) * KNN + h];
                    int   im = s_mi[(lb + s) * KNN + h];
                    if (v > bv || (v == bv && im < bi)) { bv = v; bi = im; bs = s; }
                }
            }
            g_idx[obase + kk] = bi;
            head[bs]++;
        }
    }
}

// ---------------- K3: projections ----------------
__global__ void proj_kernel(const float* __restrict__ x, const float* __restrict__ W) {
    __shared__ float s_w1[Cn][On];
    __shared__ float s_wd[Cn][On];
    __shared__ float s_x[Cn][32];

    int t = threadIdx.x;
    for (int i = t; i < On * Cn; i += 256) {
        int o = i / Cn, c = i % Cn;
        float w1 = W[o * (2 * Cn) + c];
        float w2 = W[o * (2 * Cn) + Cn + c];
        s_w1[c][o] = w1;
        s_wd[c][o] = w2 - w1;
    }
    int b  = blockIdx.x / (Nn / 32);
    int n0 = (blockIdx.x % (Nn / 32)) * 32;
    for (int i = t; i < Cn * 32; i += 256) {
        int c = i / 32, p = i % 32;
        s_x[c][p] = x[b * Cn * Nn + c * Nn + n0 + p];
    }
    __syncthreads();

    int warp = t >> 5, lane = t & 31;
    int p0 = warp * 4;
    float au0[4] = {0,0,0,0}, au1[4] = {0,0,0,0};
    float av0[4] = {0,0,0,0}, av1[4] = {0,0,0,0};

#pragma unroll 8
    for (int c = 0; c < Cn; ++c) {
        float w1l = s_w1[c][lane], w1h = s_w1[c][lane + 32];
        float wdl = s_wd[c][lane], wdh = s_wd[c][lane + 32];
#pragma unroll
        for (int pp = 0; pp < 4; ++pp) {
            float xv = s_x[c][p0 + pp];
            au0[pp] = fmaf(xv, w1l, au0[pp]);
            au1[pp] = fmaf(xv, w1h, au1[pp]);
            av0[pp] = fmaf(xv, wdl, av0[pp]);
            av1[pp] = fmaf(xv, wdh, av1[pp]);
        }
    }
#pragma unroll
    for (int pp = 0; pp < 4; ++pp) {
        int pt = b * Nn + n0 + p0 + pp;
        g_u[pt * On + lane]      = au0[pp];
        g_u[pt * On + 32 + lane] = au1[pp];
        g_v[pt * On + lane]      = av0[pp];
        g_v[pt * On + 32 + lane] = av1[pp];
    }
}

// ---------------- K0: zero stats ----------------
__global__ void zero_kernel() {
    int t = threadIdx.x;
    if (t < On) { g_sum[t] = 0.f; g_sumsq[t] = 0.f; }
}

// ---------------- K4: gather, max/min over k, stats ----------------
__global__ void maxstats_kernel(const float* __restrict__ gamma) {
    __shared__ float ssum[8][On];
    __shared__ float ssq[8][On];
    int warp = threadIdx.x >> 5, lane = threadIdx.x & 31;
    int pt = blockIdx.x * 8 + warp;
    int b = pt >> 12;

    const float* vp = g_v + pt * On;
    float v0 = vp[lane], v1 = vp[lane + 32];
    float mx0 = -INFINITY, mx1 = -INFINITY, mn0 = INFINITY, mn1 = INFINITY;
    float s0 = 0.f, s1 = 0.f, q0 = 0.f, q1 = 0.f;
    const int* ip = g_idx + pt * KNN;

#pragma unroll
    for (int k = 0; k < KNN; ++k) {
        int m = ip[k];
        const float* up = g_u + ((b << 12) + m) * On;
        float y0 = up[lane] + v0;
        float y1 = up[lane + 32] + v1;
        mx0 = fmaxf(mx0, y0); mn0 = fminf(mn0, y0);
        mx1 = fmaxf(mx1, y1); mn1 = fminf(mn1, y1);
        s0 += y0; q0 = fmaf(y0, y0, q0);
        s1 += y1; q1 = fmaf(y1, y1, q1);
    }
    float g0 = gamma[lane], g1 = gamma[lane + 32];
    g_sel[pt * On + lane]      = (g0 >= 0.f) ? mx0 : mn0;
    g_sel[pt * On + 32 + lane] = (g1 >= 0.f) ? mx1 : mn1;

    ssum[warp][lane] = s0; ssum[warp][lane + 32] = s1;
    ssq[warp][lane]  = q0; ssq[warp][lane + 32]  = q1;
    __syncthreads();
    if (threadIdx.x < On) {
        float ts = 0.f, tq = 0.f;
#pragma unroll
        for (int w = 0; w < 8; ++w) { ts += ssum[w][threadIdx.x]; tq += ssq[w][threadIdx.x]; }
        atomicAdd(&g_sum[threadIdx.x], ts);
        atomicAdd(&g_sumsq[threadIdx.x], tq);
    }
}

// ---------------- K6: BN coefficients ----------------
__global__ void bnfinal_kernel(const float* __restrict__ gamma, const float* __restrict__ beta) {
    int o = threadIdx.x;
    if (o < On) {
        const float M = (float)(Bn * Nn * KNN);
        float mean = g_sum[o] / M;
        float var  = g_sumsq[o] / M - mean * mean;
        var = fmaxf(var, 0.f);
        float a = gamma[o] * rsqrtf(var + EPSC);
        g_cA[o] = a;
        g_cB[o] = beta[o] - mean * a;
    }
}

// ---------------- K7: finalize + transpose ----------------
__global__ void finalize_kernel(float* __restrict__ out) {
    __shared__ float tile[32][On + 1];
    __shared__ float sA[On], sB[On];
    int t = threadIdx.x;
    int b  = blockIdx.x / (Nn / 32);
    int n0 = (blockIdx.x % (Nn / 32)) * 32;
    if (t < On) { sA[t] = g_cA[t]; sB[t] = g_cB[t]; }
    for (int i = t; i < 32 * On; i += 256) {
        int nl = i / On, o = i % On;
        tile[nl][o] = g_sel[(b * Nn + n0) * On + i];
    }
    __syncthreads();
    for (int i = t; i < 32 * On; i += 256) {
        int o = i / 32, nl = i % 32;
        float y = tile[nl][o];
        float val = fmaf(sA[o], y, sB[o]);
        out[b * On * Nn + o * Nn + n0 + nl] = (val >= 0.f) ? val : SLOPE * val;
    }
}

// ---------------- launch ----------------
// knn at position 4 (harness ncu -s 5 -c 1 lands there).
extern "C" void kernel_launch(void* const* d_in, const int* in_sizes, int n_in,
                              void* d_out, int out_size) {
    const float* x     = (const float*)d_in[0];
    const float* W     = (const float*)d_in[1];
    const float* gamma = (const float*)d_in[2];
    const float* beta  = (const float*)d_in[3];
    float* out = (float*)d_out;

    cudaFuncSetAttribute(knn_kernel, cudaFuncAttributeMaxDynamicSharedMemorySize, SMEM_KNN);

    xx_kernel<<<(Bn * Nn) / 256, 256>>>(x);
    split_kernel<<<Bn * (Nn / 64), 256>>>(x);
    proj_kernel<<<Bn * (Nn / 32), 256>>>(x, W);
    knn_kernel<<<Bn * (Nn / QT), 256, SMEM_KNN>>>();
    zero_kernel<<<1, 64>>>();
    maxstats_kernel<<<(Bn * Nn) / 8, 256>>>(gamma);
    bnfinal_kernel<<<1, 64>>>(gamma, beta);
    finalize_kernel<<<Bn * (Nn / 32), 256>>>(out);
}

// round 15
// speedup vs baseline: 1.9911x; 1.0766x over previous
#include <cuda_runtime.h>
#include <cuda_bf16.h>
#include <math.h>
#include <stdint.h>

#define Bn   8
#define Cn   64
#define Nn   4096
#define On   64
#define KNN  20
#define SLOPE 0.2f
#define EPSC  1e-5f

// warp-level bf16 MMA (sm_80+, baseline sm_103-safe; tcgen05 is NOT available here)
#define MMA_BF16(c, a, b0, b1) \
    asm volatile("mma.sync.aligned.m16n8k16.row.col.f32.bf16.bf16.f32 " \
        "{%0,%1,%2,%3}, {%4,%5,%6,%7}, {%8,%9}, {%0,%1,%2,%3};" \
        : "+f"((c)[0]), "+f"((c)[1]), "+f"((c)[2]), "+f"((c)[3]) \
        : "r"((a)[0]), "r"((a)[1]), "r"((a)[2]), "r"((a)[3]), "r"(b0), "r"(b1))

#define LDM_X4(r, addr) \
    asm volatile("ldmatrix.sync.aligned.m8n8.x4.shared.b16 {%0,%1,%2,%3}, [%4];" \
        : "=r"((r)[0]), "=r"((r)[1]), "=r"((r)[2]), "=r"((r)[3]) : "r"(addr))

#define CP_ASYNC16(dst, src) \
    asm volatile("cp.async.cg.shared.global [%0], [%1], 16;" :: "r"(dst), "l"(src) : "memory")
#define CP_ASYNC4(dst, src) \
    asm volatile("cp.async.ca.shared.global [%0], [%1], 4;" :: "r"(dst), "l"(src) : "memory")
#define CP_COMMIT() asm volatile("cp.async.commit_group;" ::: "memory")
#define CP_WAIT0()  asm volatile("cp.async.wait_group 0;" ::: "memory")

__device__ __forceinline__ uint32_t smem_u32(const void* p) {
    uint32_t a;
    asm("{ .reg .u64 t; cvta.to.shared.u64 t, %1; cvt.u32.u64 %0, t; }" : "=r"(a) : "l"(p));
    return a;
}

// ---------------- device scratch ----------------
__device__ float g_xx[Bn * Nn];
__device__ int   g_idx[Bn * Nn * KNN];
__device__ float g_u[Bn * Nn * On];
__device__ float g_v[Bn * Nn * On];
__device__ float g_sel[Bn * Nn * On];
__device__ float g_sum[On];
__device__ float g_sumsq[On];
__device__ float g_cA[On];
__device__ float g_cB[On];
__device__ __nv_bfloat16 g_s[Bn * Nn * 192];   // [b][n][b0|b1|b2] bf16 splits

// ---------------- K1: squared norms ----------------
__global__ void xx_kernel(const float* __restrict__ x) {
    int i = blockIdx.x * 256 + threadIdx.x;
    int b = i >> 12;
    int n = i & (Nn - 1);
    const float* xp = x + b * Cn * Nn + n;
    float s = 0.f;
#pragma unroll
    for (int c = 0; c < Cn; ++c) { float v = xp[c * Nn]; s = fmaf(v, v, s); }
    g_xx[i] = s;
}

// ---------------- K1b: bf16x3 split + transpose ----------------
__global__ void split_kernel(const float* __restrict__ x) {
    __shared__ alignas(16) __nv_bfloat16 sb0[64 * 72];
    __shared__ alignas(16) __nv_bfloat16 sb1[64 * 72];
    __shared__ alignas(16) __nv_bfloat16 sb2[64 * 72];

    int t = threadIdx.x;
    int b = blockIdx.x >> 6;
    int n0 = (blockIdx.x & 63) * 64;

#pragma unroll
    for (int j = 0; j < 16; ++j) {
        int idx = j * 256 + t;
        int c = idx >> 6, n = idx & 63;
        float v = x[b * Cn * Nn + c * Nn + n0 + n];
        __nv_bfloat16 h0 = __float2bfloat16(v);
        float f0 = __bfloat162float(h0);
        __nv_bfloat16 h1 = __float2bfloat16(v - f0);
        float f1 = __bfloat162float(h1);
        __nv_bfloat16 h2 = __float2bfloat16(v - f0 - f1);
        sb0[n * 72 + c] = h0;
        sb1[n * 72 + c] = h1;
        sb2[n * 72 + c] = h2;
    }
    __syncthreads();

    uint4* g4 = (uint4*)g_s;
#pragma unroll
    for (int j = 0; j < 6; ++j) {
        int idx = j * 256 + t;
        int r = idx / 24, u = idx % 24;
        int ch = u >> 3, c8 = (u & 7) * 8;
        const __nv_bfloat16* src = (ch == 0) ? sb0 : (ch == 1) ? sb1 : sb2;
        g4[(b * Nn + n0 + r) * 24 + u] = *(const uint4*)(src + r * 72 + c8);
    }
}

// ---------------- K2: mma.sync + cp.async + rotated-acc + gated top-K --------
#define QT 64
#define CT 64
#define SROW 400

#define OFF_A    0                     // 25600
#define OFF_B    25600                 // 2 x 25600 -> 76800
#define OFF_HXX  76800                 // 2 x 64 f  -> 77312
#define OFF_STG  77312                 // 8 warps x 32 owners x 20 f = 20480 -> 97792
#define OFF_MINV 97792                 // 64 rows x 4 subs f = 1024 -> 98816
#define SMEM_KNN 98816
#define OFF_MV   0                     // post-loop alias (A region)
#define OFF_MI   25600                 // post-loop alias (B region)

__global__ void __launch_bounds__(256, 2) knn_kernel() {
    extern __shared__ char sm[];
    uint32_t smb = smem_u32(sm);
    float* s_hxx  = (float*)(sm + OFF_HXX);
    float* s_minv = (float*)(sm + OFF_MINV);
    float* s_mv   = (float*)(sm + OFF_MV);
    int*   s_mi   = (int*)  (sm + OFF_MI);

    int t = threadIdx.x, w = t >> 5, lane = t & 31;
    int g = lane >> 2, q4 = lane & 3;
    int b = blockIdx.x >> 6;
    int n0 = (blockIdx.x & 63) * QT;

    int wrow = (w & 3) * 16;
    int ntb  = (w >= 4) ? 4 : 0;       // n-tile base (cols ntb*8)

    const uint4* gs4 = (const uint4*)g_s;
    // loader mapping: row lr = t>>2, uint4 col lu = (t&3) + 4*j
    int lr = t >> 2, lu = t & 3;
    const uint4* gA = gs4 + (size_t)(b * Nn + n0 + lr) * 24 + lu;
    const uint4* gB = gs4 + (size_t)(b * Nn + lr) * 24 + lu;
    uint32_t dstA = (uint32_t)(OFF_A + lr * SROW + lu * 16);
    uint32_t dstB = (uint32_t)(OFF_B + lr * SROW + lu * 16);
#pragma unroll
    for (int j = 0; j < 6; ++j) {
        *(uint4*)(sm + dstA + j * 64) = gA[j * 4];
        *(uint4*)(sm + dstB + j * 64) = gB[j * 4];
    }
    gB += CT * 24;                      // points at tile 1
    const float* gxxp = g_xx + b * Nn + t;
    if (t < CT) s_hxx[t] = gxxp[0];     // raw xx (x0.5 folded into staging fmaf)
    s_minv[t] = -INFINITY;
    __syncthreads();

    // ldmatrix per-lane source addresses
    uint32_t aaddr = smb + OFF_A
        + (uint32_t)((wrow + ((lane >> 3) & 1) * 8 + (lane & 7)) * SROW)
        + (uint32_t)((lane >> 4) * 16);
    uint32_t brow = (uint32_t)(ntb * 8 + (lane >> 4) * 8 + (lane & 7));
    uint32_t bk   = (uint32_t)(((lane >> 3) & 1) * 16);
    uint32_t baddr0 = smb + OFF_B + brow * SROW + bk;           // buf 0
    uint32_t baddr1 = baddr0 + 25600;                           // buf 1

    float* stg = (float*)(sm + OFF_STG) + w * 640;              // 32 owners x 20
    int og0 = (g * 2 + (q4 >> 1)) * 20;
    int og1 = ((g + 8) * 2 + (q4 >> 1)) * 20;
    int slot0 = (q4 & 1) * 2;
    int rbase = (wrow + (lane >> 1)) * 4;
    int mvslot = rbase + (ntb ? 2 : 0) + (lane & 1);
    int hxb = ntb * 8 + 2 * q4;
    const float* mystg = stg + lane * 20;

    float vals[KNN];
    int   idxs[KNN];
#pragma unroll
    for (int j = 0; j < KNN; ++j) { vals[j] = -INFINITY; idxs[j] = 0x7fffffff; }

    for (int ti = 0; ti < Nn / CT; ++ti) {
        int buf = ti & 1;
        // async prefetch of next B tile + raw hxx into the spare buffer
        if (ti < Nn / CT - 1) {
            uint32_t d = smb + dstB + (uint32_t)((buf ^ 1) * 25600);
            const char* gsrc = (const char*)gB;
#pragma unroll
            for (int j = 0; j < 6; ++j)
                CP_ASYNC16(d + j * 64, gsrc + j * 64);
            gB += CT * 24;
            if (t < CT) {
                uint32_t hd = smb + (uint32_t)(OFF_HXX + ((buf ^ 1) * 64 + t) * 4);
                CP_ASYNC4(hd, gxxp + (ti + 1) * CT);
            }
            CP_COMMIT();
        }

        // ---- MMA on current buffer (rotated across 4 accumulators) ----
        uint32_t ba = buf ? baddr1 : baddr0;
        float acc[4][4];
#pragma unroll
        for (int nt = 0; nt < 4; ++nt)
#pragma unroll
            for (int e = 0; e < 4; ++e) acc[nt][e] = 0.f;

#pragma unroll
        for (int ks = 0; ks < 4; ++ks) {
            uint32_t ak = aaddr + ks * 32;
            uint32_t bb0 = ba + ks * 32;
            uint32_t bb1 = ba + 16 * SROW + ks * 32;
            uint32_t a0[4], a1[4];
            uint32_t b0p0[4], b0p1[4], b1p0[4], b1p1[4];
            LDM_X4(a0, ak);
            LDM_X4(a1, ak + 128);
            LDM_X4(b0p0, bb0);
            LDM_X4(b0p1, bb1);
            LDM_X4(b1p0, bb0 + 128);
            LDM_X4(b1p1, bb1 + 128);
            // product b0*b0
            MMA_BF16(acc[0], a0, b0p0[0], b0p0[1]); MMA_BF16(acc[1], a0, b0p0[2], b0p0[3]);
            MMA_BF16(acc[2], a0, b0p1[0], b0p1[1]); MMA_BF16(acc[3], a0, b0p1[2], b0p1[3]);
            // product b1*b1
            MMA_BF16(acc[0], a1, b1p0[0], b1p0[1]); MMA_BF16(acc[1], a1, b1p0[2], b1p0[3]);
            MMA_BF16(acc[2], a1, b1p1[0], b1p1[1]); MMA_BF16(acc[3], a1, b1p1[2], b1p1[3]);
            // product b0*b1
            MMA_BF16(acc[0], a0, b1p0[0], b1p0[1]); MMA_BF16(acc[1], a0, b1p0[2], b1p0[3]);
            MMA_BF16(acc[2], a0, b1p1[0], b1p1[1]); MMA_BF16(acc[3], a0, b1p1[2], b1p1[3]);
            // product b1*b0
            MMA_BF16(acc[0], a1, b0p0[0], b0p0[1]); MMA_BF16(acc[1], a1, b0p0[2], b0p0[3]);
            MMA_BF16(acc[2], a1, b0p1[0], b0p1[1]); MMA_BF16(acc[3], a1, b0p1[2], b0p1[3]);
            // load a2/b2 into dead a1/b1 registers
            LDM_X4(a1, ak + 256);
            LDM_X4(b1p0, bb0 + 256);
            LDM_X4(b1p1, bb1 + 256);
            // product b0*b2
            MMA_BF16(acc[0], a0, b1p0[0], b1p0[1]); MMA_BF16(acc[1], a0, b1p0[2], b1p0[3]);
            MMA_BF16(acc[2], a0, b1p1[0], b1p1[1]); MMA_BF16(acc[3], a0, b1p1[2], b1p1[3]);
            // product b2*b0
            MMA_BF16(acc[0], a1, b0p0[0], b0p0[1]); MMA_BF16(acc[1], a1, b0p0[2], b0p0[3]);
            MMA_BF16(acc[2], a1, b0p1[0], b0p1[1]); MMA_BF16(acc[3], a1, b0p1[2], b0p1[3]);
        }

        // ---- stage (score = I - 0.5*xx), warp-local ----
#pragma unroll
        for (int nt = 0; nt < 4; ++nt) {
            float2 hx = *(const float2*)(s_hxx + buf * 64 + hxb + nt * 8);
            *(float2*)(stg + og0 + nt * 4 + slot0) =
                make_float2(fmaf(-0.5f, hx.x, acc[nt][0]), fmaf(-0.5f, hx.y, acc[nt][1]));
            *(float2*)(stg + og1 + nt * 4 + slot0) =
                make_float2(fmaf(-0.5f, hx.x, acc[nt][2]), fmaf(-0.5f, hx.y, acc[nt][3]));
        }
        __syncwarp();

        // ---- owner scan: lane o = (row<<1)|colsub ----
        const float4* sp = (const float4*)mystg;
        float4 v0 = sp[0], v1 = sp[1], v2 = sp[2], v3 = sp[3];
        float tmax = fmaxf(
            fmaxf(fmaxf(fmaxf(v0.x, v0.y), fmaxf(v0.z, v0.w)),
                  fmaxf(fmaxf(v1.x, v1.y), fmaxf(v1.z, v1.w))),
            fmaxf(fmaxf(fmaxf(v2.x, v2.y), fmaxf(v2.z, v2.w)),
                  fmaxf(fmaxf(v3.x, v3.y), fmaxf(v3.z, v3.w))));
        float thr = fmaxf(fmaxf(s_minv[rbase], s_minv[rbase + 1]),
                          fmaxf(s_minv[rbase + 2], s_minv[rbase + 3]));
        float thr_eff = fmaxf(thr, vals[KNN - 1]);
        if (tmax > thr_eff) {
            unsigned qm = 0;
            qm |= (v0.x > thr_eff) ? 0x0001u : 0u;
            qm |= (v0.y > thr_eff) ? 0x0002u : 0u;
            qm |= (v0.z > thr_eff) ? 0x0004u : 0u;
            qm |= (v0.w > thr_eff) ? 0x0008u : 0u;
            qm |= (v1.x > thr_eff) ? 0x0010u : 0u;
            qm |= (v1.y > thr_eff) ? 0x0020u : 0u;
            qm |= (v1.z > thr_eff) ? 0x0040u : 0u;
            qm |= (v1.w > thr_eff) ? 0x0080u : 0u;
            qm |= (v2.x > thr_eff) ? 0x0100u : 0u;
            qm |= (v2.y > thr_eff) ? 0x0200u : 0u;
            qm |= (v2.z > thr_eff) ? 0x0400u : 0u;
            qm |= (v2.w > thr_eff) ? 0x0800u : 0u;
            qm |= (v3.x > thr_eff) ? 0x1000u : 0u;
            qm |= (v3.y > thr_eff) ? 0x2000u : 0u;
            qm |= (v3.z > thr_eff) ? 0x4000u : 0u;
            qm |= (v3.w > thr_eff) ? 0x8000u : 0u;

            int mbase = ti * CT + ntb * 8 + 4 * (lane & 1);
            while (qm) {
                int j = __ffs(qm) - 1;
                qm &= qm - 1;
                float v = mystg[j];
                if (v > vals[KNN - 1] && v > thr) {
                    vals[KNN - 1] = v;
                    idxs[KNN - 1] = mbase + ((j >> 2) << 3) + (j & 3);
#pragma unroll
                    for (int q = KNN - 1; q > 0; --q) {
                        bool sw = vals[q] > vals[q - 1];
                        float tv = sw ? vals[q - 1] : vals[q];
                        float tu = sw ? vals[q]     : vals[q - 1];
                        int   ta = sw ? idxs[q - 1] : idxs[q];
                        int   tb = sw ? idxs[q]     : idxs[q - 1];
                        vals[q] = tv; vals[q - 1] = tu;
                        idxs[q] = ta; idxs[q - 1] = tb;
                    }
                }
            }
            s_minv[mvslot] = vals[KNN - 1];
        }
        CP_WAIT0();        // async B/hxx copies landed
        __syncthreads();   // B-buf + staging reuse barrier
    }

    // ---- dump lists, 4-way merge per row ----
    int owner_id = rbase + (ntb ? 2 : 0) + (lane & 1);   // row*4 + sub
#pragma unroll
    for (int j = 0; j < KNN; ++j) {
        s_mv[owner_id * KNN + j] = vals[j];
        s_mi[owner_id * KNN + j] = idxs[j];
    }
    __syncthreads();

    if (t < QT) {
        int head[4] = {0, 0, 0, 0};
        int lb = t * 4;
        int obase = (b * Nn + n0 + t) * KNN;
        for (int kk = 0; kk < KNN; ++kk) {
            float bv = -INFINITY; int bi = 0x7fffffff; int bs = 0;
#pragma unroll
            for (int s = 0; s < 4; ++s) {
                int h = head[s];
                if (h < KNN) {
                    float v  = s_mv[(lb + s) * KNN + h];
                    int   im = s_mi[(lb + s) * KNN + h];
                    if (v > bv || (v == bv && im < bi)) { bv = v; bi = im; bs = s; }
                }
            }
            g_idx[obase + kk] = bi;
            head[bs]++;
        }
    }
}

// ---------------- K3: projections ----------------
__global__ void proj_kernel(const float* __restrict__ x, const float* __restrict__ W) {
    __shared__ float s_w1[Cn][On];
    __shared__ float s_wd[Cn][On];
    __shared__ float s_x[Cn][32];

    int t = threadIdx.x;
    for (int i = t; i < On * Cn; i += 256) {
        int o = i / Cn, c = i % Cn;
        float w1 = W[o * (2 * Cn) + c];
        float w2 = W[o * (2 * Cn) + Cn + c];
        s_w1[c][o] = w1;
        s_wd[c][o] = w2 - w1;
    }
    int b  = blockIdx.x / (Nn / 32);
    int n0 = (blockIdx.x % (Nn / 32)) * 32;
    for (int i = t; i < Cn * 32; i += 256) {
        int c = i / 32, p = i % 32;
        s_x[c][p] = x[b * Cn * Nn + c * Nn + n0 + p];
    }
    __syncthreads();

    int warp = t >> 5, lane = t & 31;
    int p0 = warp * 4;
    float au0[4] = {0,0,0,0}, au1[4] = {0,0,0,0};
    float av0[4] = {0,0,0,0}, av1[4] = {0,0,0,0};

#pragma unroll 8
    for (int c = 0; c < Cn; ++c) {
        float w1l = s_w1[c][lane], w1h = s_w1[c][lane + 32];
        float wdl = s_wd[c][lane], wdh = s_wd[c][lane + 32];
#pragma unroll
        for (int pp = 0; pp < 4; ++pp) {
            float xv = s_x[c][p0 + pp];
            au0[pp] = fmaf(xv, w1l, au0[pp]);
            au1[pp] = fmaf(xv, w1h, au1[pp]);
            av0[pp] = fmaf(xv, wdl, av0[pp]);
            av1[pp] = fmaf(xv, wdh, av1[pp]);
        }
    }
#pragma unroll
    for (int pp = 0; pp < 4; ++pp) {
        int pt = b * Nn + n0 + p0 + pp;
        g_u[pt * On + lane]      = au0[pp];
        g_u[pt * On + 32 + lane] = au1[pp];
        g_v[pt * On + lane]      = av0[pp];
        g_v[pt * On + 32 + lane] = av1[pp];
    }
}

// ---------------- K0: zero stats ----------------
__global__ void zero_kernel() {
    int t = threadIdx.x;
    if (t < On) { g_sum[t] = 0.f; g_sumsq[t] = 0.f; }
}

// ---------------- K4: gather, max/min over k, stats ----------------
__global__ void maxstats_kernel(const float* __restrict__ gamma) {
    __shared__ float ssum[8][On];
    __shared__ float ssq[8][On];
    int warp = threadIdx.x >> 5, lane = threadIdx.x & 31;
    int pt = blockIdx.x * 8 + warp;
    int b = pt >> 12;

    const float* vp = g_v + pt * On;
    float v0 = vp[lane], v1 = vp[lane + 32];
    float mx0 = -INFINITY, mx1 = -INFINITY, mn0 = INFINITY, mn1 = INFINITY;
    float s0 = 0.f, s1 = 0.f, q0 = 0.f, q1 = 0.f;
    const int* ip = g_idx + pt * KNN;

#pragma unroll
    for (int k = 0; k < KNN; ++k) {
        int m = ip[k];
        const float* up = g_u + ((b << 12) + m) * On;
        float y0 = up[lane] + v0;
        float y1 = up[lane + 32] + v1;
        mx0 = fmaxf(mx0, y0); mn0 = fminf(mn0, y0);
        mx1 = fmaxf(mx1, y1); mn1 = fminf(mn1, y1);
        s0 += y0; q0 = fmaf(y0, y0, q0);
        s1 += y1; q1 = fmaf(y1, y1, q1);
    }
    float g0 = gamma[lane], g1 = gamma[lane + 32];
    g_sel[pt * On + lane]      = (g0 >= 0.f) ? mx0 : mn0;
    g_sel[pt * On + 32 + lane] = (g1 >= 0.f) ? mx1 : mn1;

    ssum[warp][lane] = s0; ssum[warp][lane + 32] = s1;
    ssq[warp][lane]  = q0; ssq[warp][lane + 32]  = q1;
    __syncthreads();
    if (threadIdx.x < On) {
        float ts = 0.f, tq = 0.f;
#pragma unroll
        for (int w = 0; w < 8; ++w) { ts += ssum[w][threadIdx.x]; tq += ssq[w][threadIdx.x]; }
        atomicAdd(&g_sum[threadIdx.x], ts);
        atomicAdd(&g_sumsq[threadIdx.x], tq);
    }
}

// ---------------- K6: BN coefficients ----------------
__global__ void bnfinal_kernel(const float* __restrict__ gamma, const float* __restrict__ beta) {
    int o = threadIdx.x;
    if (o < On) {
        const float M = (float)(Bn * Nn * KNN);
        float mean = g_sum[o] / M;
        float var  = g_sumsq[o] / M - mean * mean;
        var = fmaxf(var, 0.f);
        float a = gamma[o] * rsqrtf(var + EPSC);
        g_cA[o] = a;
        g_cB[o] = beta[o] - mean * a;
    }
}

// ---------------- K7: finalize + transpose ----------------
__global__ void finalize_kernel(float* __restrict__ out) {
    __shared__ float tile[32][On + 1];
    __shared__ float sA[On], sB[On];
    int t = threadIdx.x;
    int b  = blockIdx.x / (Nn / 32);
    int n0 = (blockIdx.x % (Nn / 32)) * 32;
    if (t < On) { sA[t] = g_cA[t]; sB[t] = g_cB[t]; }
    for (int i = t; i < 32 * On; i += 256) {
        int nl = i / On, o = i % On;
        tile[nl][o] = g_sel[(b * Nn + n0) * On + i];
    }
    __syncthreads();
    for (int i = t; i < 32 * On; i += 256) {
        int o = i / 32, nl = i % 32;
        float y = tile[nl][o];
        float val = fmaf(sA[o], y, sB[o]);
        out[b * On * Nn + o * Nn + n0 + nl] = (val >= 0.f) ? val : SLOPE * val;
    }
}

// ---------------- launch ----------------
// knn at position 4 (harness ncu -s 5 -c 1 lands there).
extern "C" void kernel_launch(void* const* d_in, const int* in_sizes, int n_in,
                              void* d_out, int out_size) {
    const float* x     = (const float*)d_in[0];
    const float* W     = (const float*)d_in[1];
    const float* gamma = (const float*)d_in[2];
    const float* beta  = (const float*)d_in[3];
    float* out = (float*)d_out;

    cudaFuncSetAttribute(knn_kernel, cudaFuncAttributeMaxDynamicSharedMemorySize, SMEM_KNN);

    xx_kernel<<<(Bn * Nn) / 256, 256>>>(x);
    split_kernel<<<Bn * (Nn / 64), 256>>>(x);
    proj_kernel<<<Bn * (Nn / 32), 256>>>(x, W);
    knn_kernel<<<Bn * (Nn / QT), 256, SMEM_KNN>>>();
    zero_kernel<<<1, 64>>>();
    maxstats_kernel<<<(Bn * Nn) / 8, 256>>>(gamma);
    bnfinal_kernel<<<1, 64>>>(gamma, beta);
    finalize_kernel<<<Bn * (Nn / 32), 256>>>(out);
}

// round 16
// speedup vs baseline: 2.2978x; 1.1540x over previous
#include <cuda_runtime.h>
#include <cuda_fp16.h>
#include <math.h>
#include <stdint.h>

#define Bn   8
#define Cn   64
#define Nn   4096
#define On   64
#define KNN  20
#define SLOPE 0.2f
#define EPSC  1e-5f

// warp-level fp16 MMA (sm_80+, baseline sm_103-safe; tcgen05 is NOT available here)
#define MMA_F16(c, a, b0, b1) \
    asm volatile("mma.sync.aligned.m16n8k16.row.col.f32.f16.f16.f32 " \
        "{%0,%1,%2,%3}, {%4,%5,%6,%7}, {%8,%9}, {%0,%1,%2,%3};" \
        : "+f"((c)[0]), "+f"((c)[1]), "+f"((c)[2]), "+f"((c)[3]) \
        : "r"((a)[0]), "r"((a)[1]), "r"((a)[2]), "r"((a)[3]), "r"(b0), "r"(b1))

#define LDM_X4(r, addr) \
    asm volatile("ldmatrix.sync.aligned.m8n8.x4.shared.b16 {%0,%1,%2,%3}, [%4];" \
        : "=r"((r)[0]), "=r"((r)[1]), "=r"((r)[2]), "=r"((r)[3]) : "r"(addr))

#define CP_ASYNC16(dst, src) \
    asm volatile("cp.async.cg.shared.global [%0], [%1], 16;" :: "r"(dst), "l"(src) : "memory")
#define CP_ASYNC4(dst, src) \
    asm volatile("cp.async.ca.shared.global [%0], [%1], 4;" :: "r"(dst), "l"(src) : "memory")
#define CP_COMMIT() asm volatile("cp.async.commit_group;" ::: "memory")
#define CP_WAIT0()  asm volatile("cp.async.wait_group 0;" ::: "memory")

__device__ __forceinline__ uint32_t smem_u32(const void* p) {
    uint32_t a;
    asm("{ .reg .u64 t; cvta.to.shared.u64 t, %1; cvt.u32.u64 %0, t; }" : "=r"(a) : "l"(p));
    return a;
}

// ---------------- device scratch ----------------
__device__ float g_xx[Bn * Nn];
__device__ int   g_idx[Bn * Nn * KNN];
__device__ float g_u[Bn * Nn * On];
__device__ float g_v[Bn * Nn * On];
__device__ float g_sel[Bn * Nn * On];
__device__ float g_sum[On];
__device__ float g_sumsq[On];
__device__ float g_cA[On];
__device__ float g_cB[On];
__device__ __half g_s[Bn * Nn * 128];   // [b][n][h0(64)|h1(64)] fp16 splits

// ---------------- K1: squared norms ----------------
__global__ void xx_kernel(const float* __restrict__ x) {
    int i = blockIdx.x * 256 + threadIdx.x;
    int b = i >> 12;
    int n = i & (Nn - 1);
    const float* xp = x + b * Cn * Nn + n;
    float s = 0.f;
#pragma unroll
    for (int c = 0; c < Cn; ++c) { float v = xp[c * Nn]; s = fmaf(v, v, s); }
    g_xx[i] = s;
}

// ---------------- K1b: fp16x2 split + transpose ----------------
// out row [n]: [h0(64 fp16) | h1(64 fp16)] = 256 B; h0+h1 = x to ~2^-22.
__global__ void split_kernel(const float* __restrict__ x) {
    __shared__ alignas(16) __half sb0[64 * 72];
    __shared__ alignas(16) __half sb1[64 * 72];

    int t = threadIdx.x;
    int b = blockIdx.x >> 6;
    int n0 = (blockIdx.x & 63) * 64;

#pragma unroll
    for (int j = 0; j < 16; ++j) {
        int idx = j * 256 + t;
        int c = idx >> 6, n = idx & 63;
        float v = x[b * Cn * Nn + c * Nn + n0 + n];
        __half h0 = __float2half_rn(v);
        __half h1 = __float2half_rn(v - __half2float(h0));
        sb0[n * 72 + c] = h0;
        sb1[n * 72 + c] = h1;
    }
    __syncthreads();

    uint4* g4 = (uint4*)g_s;
#pragma unroll
    for (int j = 0; j < 4; ++j) {
        int idx = j * 256 + t;          // 1024 = 64 rows x 16 uint4
        int r = idx >> 4, u = idx & 15;
        int ch = u >> 3, c8 = (u & 7) * 8;
        const __half* src = ch ? sb1 : sb0;
        g4[(b * Nn + n0 + r) * 16 + u] = *(const uint4*)(src + r * 72 + c8);
    }
}

// ---------------- K2: fp16x2 4-product mma.sync + gated top-K ----------------
#define QT 64
#define CT 64
#define SROW 272                        // 256 B data + 16 pad (conflict-free LDSM)
#define BTILE 17408                     // 64 * SROW

#define OFF_A    0                      // 17408
#define OFF_B    17408                  // 2 x 17408 -> 52224
#define OFF_HXX  52224                  // 2 x 64 f  -> 52736
#define OFF_STG  52736                  // 8 warps x 32 owners x 20 f -> 73216
#define OFF_MINV 73216                  // -> 74240
#define SMEM_KNN 74240
#define OFF_MV   0                      // post-loop alias
#define OFF_MI   20480                  // post-loop alias

__global__ void __launch_bounds__(256, 2) knn_kernel() {
    extern __shared__ char sm[];
    uint32_t smb = smem_u32(sm);
    float* s_hxx  = (float*)(sm + OFF_HXX);
    float* s_minv = (float*)(sm + OFF_MINV);
    float* s_mv   = (float*)(sm + OFF_MV);
    int*   s_mi   = (int*)  (sm + OFF_MI);

    int t = threadIdx.x, w = t >> 5, lane = t & 31;
    int g = lane >> 2, q4 = lane & 3;
    int b = blockIdx.x >> 6;
    int n0 = (blockIdx.x & 63) * QT;

    int wrow = (w & 3) * 16;
    int ntb  = (w >= 4) ? 4 : 0;

    const uint4* gs4 = (const uint4*)g_s;
    // loader: row lr = t>>2, uint4 col lu = (t&3) + 4*j  (16 uint4/row)
    int lr = t >> 2, lu = t & 3;
    const uint4* gA = gs4 + (size_t)(b * Nn + n0 + lr) * 16 + lu;
    const uint4* gB = gs4 + (size_t)(b * Nn + lr) * 16 + lu;
    uint32_t dstA = (uint32_t)(OFF_A + lr * SROW + lu * 16);
    uint32_t dstB = (uint32_t)(OFF_B + lr * SROW + lu * 16);
#pragma unroll
    for (int j = 0; j < 4; ++j) {
        *(uint4*)(sm + dstA + j * 64) = gA[j * 4];
        *(uint4*)(sm + dstB + j * 64) = gB[j * 4];
    }
    gB += CT * 16;                      // points at tile 1
    const float* gxxp = g_xx + b * Nn + t;
    if (t < CT) s_hxx[t] = gxxp[0];     // raw xx (x0.5 folded into staging fmaf)
    s_minv[t] = -INFINITY;
    __syncthreads();

    // ldmatrix per-lane source addresses
    uint32_t aaddr = smb + OFF_A
        + (uint32_t)((wrow + ((lane >> 3) & 1) * 8 + (lane & 7)) * SROW)
        + (uint32_t)((lane >> 4) * 16);
    uint32_t brow = (uint32_t)(ntb * 8 + (lane >> 4) * 8 + (lane & 7));
    uint32_t bk   = (uint32_t)(((lane >> 3) & 1) * 16);
    uint32_t baddr0 = smb + OFF_B + brow * SROW + bk;
    uint32_t baddr1 = baddr0 + BTILE;

    float* stg = (float*)(sm + OFF_STG) + w * 640;              // 32 owners x 20
    int og0 = (g * 2 + (q4 >> 1)) * 20;
    int og1 = ((g + 8) * 2 + (q4 >> 1)) * 20;
    int slot0 = (q4 & 1) * 2;
    int rbase = (wrow + (lane >> 1)) * 4;
    int mvslot = rbase + (ntb ? 2 : 0) + (lane & 1);
    int hxb = ntb * 8 + 2 * q4;
    const float* mystg = stg + lane * 20;

    float vals[KNN];
    int   idxs[KNN];
#pragma unroll
    for (int j = 0; j < KNN; ++j) { vals[j] = -INFINITY; idxs[j] = 0x7fffffff; }

    for (int ti = 0; ti < Nn / CT; ++ti) {
        int buf = ti & 1;
        // async prefetch of next B tile + raw hxx into the spare buffer
        if (ti < Nn / CT - 1) {
            uint32_t d = smb + dstB + (uint32_t)((buf ^ 1) * BTILE);
            const char* gsrc = (const char*)gB;
#pragma unroll
            for (int j = 0; j < 4; ++j)
                CP_ASYNC16(d + j * 64, gsrc + j * 64);
            gB += CT * 16;
            if (t < CT) {
                uint32_t hd = smb + (uint32_t)(OFF_HXX + ((buf ^ 1) * 64 + t) * 4);
                CP_ASYNC4(hd, gxxp + (ti + 1) * CT);
            }
            CP_COMMIT();
        }

        // ---- MMA: 4 products (h0g0, h1g1, h0g1, h1g0), rotated over 4 accs ----
        uint32_t ba = buf ? baddr1 : baddr0;
        float acc[4][4];
#pragma unroll
        for (int nt = 0; nt < 4; ++nt)
#pragma unroll
            for (int e = 0; e < 4; ++e) acc[nt][e] = 0.f;

#pragma unroll
        for (int ks = 0; ks < 4; ++ks) {
            uint32_t ak  = aaddr + ks * 32;
            uint32_t bb0 = ba + ks * 32;
            uint32_t bb1 = ba + 16 * SROW + ks * 32;
            uint32_t a0[4], a1[4];
            uint32_t g0p0[4], g0p1[4], g1p0[4], g1p1[4];
            LDM_X4(a0, ak);                 // h0
            LDM_X4(a1, ak + 128);           // h1
            LDM_X4(g0p0, bb0);              // g0, cols 0-15
            LDM_X4(g0p1, bb1);              // g0, cols 16-31
            LDM_X4(g1p0, bb0 + 128);        // g1, cols 0-15
            LDM_X4(g1p1, bb1 + 128);        // g1, cols 16-31
            // h0*g0
            MMA_F16(acc[0], a0, g0p0[0], g0p0[1]); MMA_F16(acc[1], a0, g0p0[2], g0p0[3]);
            MMA_F16(acc[2], a0, g0p1[0], g0p1[1]); MMA_F16(acc[3], a0, g0p1[2], g0p1[3]);
            // h1*g1
            MMA_F16(acc[0], a1, g1p0[0], g1p0[1]); MMA_F16(acc[1], a1, g1p0[2], g1p0[3]);
            MMA_F16(acc[2], a1, g1p1[0], g1p1[1]); MMA_F16(acc[3], a1, g1p1[2], g1p1[3]);
            // h0*g1
            MMA_F16(acc[0], a0, g1p0[0], g1p0[1]); MMA_F16(acc[1], a0, g1p0[2], g1p0[3]);
            MMA_F16(acc[2], a0, g1p1[0], g1p1[1]); MMA_F16(acc[3], a0, g1p1[2], g1p1[3]);
            // h1*g0
            MMA_F16(acc[0], a1, g0p0[0], g0p0[1]); MMA_F16(acc[1], a1, g0p0[2], g0p0[3]);
            MMA_F16(acc[2], a1, g0p1[0], g0p1[1]); MMA_F16(acc[3], a1, g0p1[2], g0p1[3]);
        }

        // ---- stage (score = I - 0.5*xx), warp-local ----
#pragma unroll
        for (int nt = 0; nt < 4; ++nt) {
            float2 hx = *(const float2*)(s_hxx + buf * 64 + hxb + nt * 8);
            *(float2*)(stg + og0 + nt * 4 + slot0) =
                make_float2(fmaf(-0.5f, hx.x, acc[nt][0]), fmaf(-0.5f, hx.y, acc[nt][1]));
            *(float2*)(stg + og1 + nt * 4 + slot0) =
                make_float2(fmaf(-0.5f, hx.x, acc[nt][2]), fmaf(-0.5f, hx.y, acc[nt][3]));
        }
        __syncwarp();

        // ---- owner scan ----
        const float4* sp = (const float4*)mystg;
        float4 v0 = sp[0], v1 = sp[1], v2 = sp[2], v3 = sp[3];
        float tmax = fmaxf(
            fmaxf(fmaxf(fmaxf(v0.x, v0.y), fmaxf(v0.z, v0.w)),
                  fmaxf(fmaxf(v1.x, v1.y), fmaxf(v1.z, v1.w))),
            fmaxf(fmaxf(fmaxf(v2.x, v2.y), fmaxf(v2.z, v2.w)),
                  fmaxf(fmaxf(v3.x, v3.y), fmaxf(v3.z, v3.w))));
        float thr = fmaxf(fmaxf(s_minv[rbase], s_minv[rbase + 1]),
                          fmaxf(s_minv[rbase + 2], s_minv[rbase + 3]));
        float thr_eff = fmaxf(thr, vals[KNN - 1]);
        if (tmax > thr_eff) {
            unsigned qm = 0;
            qm |= (v0.x > thr_eff) ? 0x0001u : 0u;
            qm |= (v0.y > thr_eff) ? 0x0002u : 0u;
            qm |= (v0.z > thr_eff) ? 0x0004u : 0u;
            qm |= (v0.w > thr_eff) ? 0x0008u : 0u;
            qm |= (v1.x > thr_eff) ? 0x0010u : 0u;
            qm |= (v1.y > thr_eff) ? 0x0020u : 0u;
            qm |= (v1.z > thr_eff) ? 0x0040u : 0u;
            qm |= (v1.w > thr_eff) ? 0x0080u : 0u;
            qm |= (v2.x > thr_eff) ? 0x0100u : 0u;
            qm |= (v2.y > thr_eff) ? 0x0200u : 0u;
            qm |= (v2.z > thr_eff) ? 0x0400u : 0u;
            qm |= (v2.w > thr_eff) ? 0x0800u : 0u;
            qm |= (v3.x > thr_eff) ? 0x1000u : 0u;
            qm |= (v3.y > thr_eff) ? 0x2000u : 0u;
            qm |= (v3.z > thr_eff) ? 0x4000u : 0u;
            qm |= (v3.w > thr_eff) ? 0x8000u : 0u;

            int mbase = ti * CT + ntb * 8 + 4 * (lane & 1);
            while (qm) {
                int j = __ffs(qm) - 1;
                qm &= qm - 1;
                float v = mystg[j];
                if (v > vals[KNN - 1] && v > thr) {
                    vals[KNN - 1] = v;
                    idxs[KNN - 1] = mbase + ((j >> 2) << 3) + (j & 3);
#pragma unroll
                    for (int q = KNN - 1; q > 0; --q) {
                        bool sw = vals[q] > vals[q - 1];
                        float tv = sw ? vals[q - 1] : vals[q];
                        float tu = sw ? vals[q]     : vals[q - 1];
                        int   ta = sw ? idxs[q - 1] : idxs[q];
                        int   tb = sw ? idxs[q]     : idxs[q - 1];
                        vals[q] = tv; vals[q - 1] = tu;
                        idxs[q] = ta; idxs[q - 1] = tb;
                    }
                }
            }
            s_minv[mvslot] = vals[KNN - 1];
        }
        CP_WAIT0();        // async B/hxx copies landed
        __syncthreads();   // B-buf + staging reuse barrier
    }

    // ---- dump lists, 4-way merge per row ----
    int owner_id = rbase + (ntb ? 2 : 0) + (lane & 1);
#pragma unroll
    for (int j = 0; j < KNN; ++j) {
        s_mv[owner_id * KNN + j] = vals[j];
        s_mi[owner_id * KNN + j] = idxs[j];
    }
    __syncthreads();

    if (t < QT) {
        int head[4] = {0, 0, 0, 0};
        int lb = t * 4;
        int obase = (b * Nn + n0 + t) * KNN;
        for (int kk = 0; kk < KNN; ++kk) {
            float bv = -INFINITY; int bi = 0x7fffffff; int bs = 0;
#pragma unroll
            for (int s = 0; s < 4; ++s) {
                int h = head[s];
                if (h < KNN) {
                    float v  = s_mv[(lb + s) * KNN + h];
                    int   im = s_mi[(lb + s) * KNN + h];
                    if (v > bv || (v == bv && im < bi)) { bv = v; bi = im; bs = s; }
                }
            }
            g_idx[obase + kk] = bi;
            head[bs]++;
        }
    }
}

// ---------------- K3: projections ----------------
__global__ void proj_kernel(const float* __restrict__ x, const float* __restrict__ W) {
    __shared__ float s_w1[Cn][On];
    __shared__ float s_wd[Cn][On];
    __shared__ float s_x[Cn][32];

    int t = threadIdx.x;
    for (int i = t; i < On * Cn; i += 256) {
        int o = i / Cn, c = i % Cn;
        float w1 = W[o * (2 * Cn) + c];
        float w2 = W[o * (2 * Cn) + Cn + c];
        s_w1[c][o] = w1;
        s_wd[c][o] = w2 - w1;
    }
    int b  = blockIdx.x / (Nn / 32);
    int n0 = (blockIdx.x % (Nn / 32)) * 32;
    for (int i = t; i < Cn * 32; i += 256) {
        int c = i / 32, p = i % 32;
        s_x[c][p] = x[b * Cn * Nn + c * Nn + n0 + p];
    }
    __syncthreads();

    int warp = t >> 5, lane = t & 31;
    int p0 = warp * 4;
    float au0[4] = {0,0,0,0}, au1[4] = {0,0,0,0};
    float av0[4] = {0,0,0,0}, av1[4] = {0,0,0,0};

#pragma unroll 8
    for (int c = 0; c < Cn; ++c) {
        float w1l = s_w1[c][lane], w1h = s_w1[c][lane + 32];
        float wdl = s_wd[c][lane], wdh = s_wd[c][lane + 32];
#pragma unroll
        for (int pp = 0; pp < 4; ++pp) {
            float xv = s_x[c][p0 + pp];
            au0[pp] = fmaf(xv, w1l, au0[pp]);
            au1[pp] = fmaf(xv, w1h, au1[pp]);
            av0[pp] = fmaf(xv, wdl, av0[pp]);
            av1[pp] = fmaf(xv, wdh, av1[pp]);
        }
    }
#pragma unroll
    for (int pp = 0; pp < 4; ++pp) {
        int pt = b * Nn + n0 + p0 + pp;
        g_u[pt * On + lane]      = au0[pp];
        g_u[pt * On + 32 + lane] = au1[pp];
        g_v[pt * On + lane]      = av0[pp];
        g_v[pt * On + 32 + lane] = av1[pp];
    }
}

// ---------------- K0: zero stats ----------------
__global__ void zero_kernel() {
    int t = threadIdx.x;
    if (t < On) { g_sum[t] = 0.f; g_sumsq[t] = 0.f; }
}

// ---------------- K4: gather, max/min over k, stats ----------------
__global__ void maxstats_kernel(const float* __restrict__ gamma) {
    __shared__ float ssum[8][On];
    __shared__ float ssq[8][On];
    int warp = threadIdx.x >> 5, lane = threadIdx.x & 31;
    int pt = blockIdx.x * 8 + warp;
    int b = pt >> 12;

    const float* vp = g_v + pt * On;
    float v0 = vp[lane], v1 = vp[lane + 32];
    float mx0 = -INFINITY, mx1 = -INFINITY, mn0 = INFINITY, mn1 = INFINITY;
    float s0 = 0.f, s1 = 0.f, q0 = 0.f, q1 = 0.f;
    const int* ip = g_idx + pt * KNN;

#pragma unroll
    for (int k = 0; k < KNN; ++k) {
        int m = ip[k];
        const float* up = g_u + ((b << 12) + m) * On;
        float y0 = up[lane] + v0;
        float y1 = up[lane + 32] + v1;
        mx0 = fmaxf(mx0, y0); mn0 = fminf(mn0, y0);
        mx1 = fmaxf(mx1, y1); mn1 = fminf(mn1, y1);
        s0 += y0; q0 = fmaf(y0, y0, q0);
        s1 += y1; q1 = fmaf(y1, y1, q1);
    }
    float g0 = gamma[lane], g1 = gamma[lane + 32];
    g_sel[pt * On + lane]      = (g0 >= 0.f) ? mx0 : mn0;
    g_sel[pt * On + 32 + lane] = (g1 >= 0.f) ? mx1 : mn1;

    ssum[warp][lane] = s0; ssum[warp][lane + 32] = s1;
    ssq[warp][lane]  = q0; ssq[warp][lane + 32]  = q1;
    __syncthreads();
    if (threadIdx.x < On) {
        float ts = 0.f, tq = 0.f;
#pragma unroll
        for (int w = 0; w < 8; ++w) { ts += ssum[w][threadIdx.x]; tq += ssq[w][threadIdx.x]; }
        atomicAdd(&g_sum[threadIdx.x], ts);
        atomicAdd(&g_sumsq[threadIdx.x], tq);
    }
}

// ---------------- K6: BN coefficients ----------------
__global__ void bnfinal_kernel(const float* __restrict__ gamma, const float* __restrict__ beta) {
    int o = threadIdx.x;
    if (o < On) {
        const float M = (float)(Bn * Nn * KNN);
        float mean = g_sum[o] / M;
        float var  = g_sumsq[o] / M - mean * mean;
        var = fmaxf(var, 0.f);
        float a = gamma[o] * rsqrtf(var + EPSC);
        g_cA[o] = a;
        g_cB[o] = beta[o] - mean * a;
    }
}

// ---------------- K7: finalize + transpose ----------------
__global__ void finalize_kernel(float* __restrict__ out) {
    __shared__ float tile[32][On + 1];
    __shared__ float sA[On], sB[On];
    int t = threadIdx.x;
    int b  = blockIdx.x / (Nn / 32);
    int n0 = (blockIdx.x % (Nn / 32)) * 32;
    if (t < On) { sA[t] = g_cA[t]; sB[t] = g_cB[t]; }
    for (int i = t; i < 32 * On; i += 256) {
        int nl = i / On, o = i % On;
        tile[nl][o] = g_sel[(b * Nn + n0) * On + i];
    }
    __syncthreads();
    for (int i = t; i < 32 * On; i += 256) {
        int o = i / 32, nl = i % 32;
        float y = tile[nl][o];
        float val = fmaf(sA[o], y, sB[o]);
        out[b * On * Nn + o * Nn + n0 + nl] = (val >= 0.f) ? val : SLOPE * val;
    }
}

// ---------------- launch ----------------
// knn at position 4 (harness ncu -s 5 -c 1 lands there).
extern "C" void kernel_launch(void* const* d_in, const int* in_sizes, int n_in,
                              void* d_out, int out_size) {
    const float* x     = (const float*)d_in[0];
    const float* W     = (const float*)d_in[1];
    const float* gamma = (const float*)d_in[2];
    const float* beta  = (const float*)d_in[3];
    float* out = (float*)d_out;

    cudaFuncSetAttribute(knn_kernel, cudaFuncAttributeMaxDynamicSharedMemorySize, SMEM_KNN);

    xx_kernel<<<(Bn * Nn) / 256, 256>>>(x);
    split_kernel<<<Bn * (Nn / 64), 256>>>(x);
    proj_kernel<<<Bn * (Nn / 32), 256>>>(x, W);
    knn_kernel<<<Bn * (Nn / QT), 256, SMEM_KNN>>>();
    zero_kernel<<<1, 64>>>();
    maxstats_kernel<<<(Bn * Nn) / 8, 256>>>(gamma);
    bnfinal_kernel<<<1, 64>>>(gamma, beta);
    finalize_kernel<<<Bn * (Nn / 32), 256>>>(out);
}

// round 17
// speedup vs baseline: 2.3253x; 1.0120x over previous
#include <cuda_runtime.h>
#include <cuda_fp16.h>
#include <math.h>
#include <stdint.h>

#define Bn   8
#define Cn   64
#define Nn   4096
#define On   64
#define KNN  20
#define SLOPE 0.2f
#define EPSC  1e-5f

// warp-level fp16 MMA (sm_80+, baseline sm_103-safe; tcgen05 is NOT available here)
#define MMA_F16(c, a, b0, b1) \
    asm volatile("mma.sync.aligned.m16n8k16.row.col.f32.f16.f16.f32 " \
        "{%0,%1,%2,%3}, {%4,%5,%6,%7}, {%8,%9}, {%0,%1,%2,%3};" \
        : "+f"((c)[0]), "+f"((c)[1]), "+f"((c)[2]), "+f"((c)[3]) \
        : "r"((a)[0]), "r"((a)[1]), "r"((a)[2]), "r"((a)[3]), "r"(b0), "r"(b1))

#define LDM_X4(r, addr) \
    asm volatile("ldmatrix.sync.aligned.m8n8.x4.shared.b16 {%0,%1,%2,%3}, [%4];" \
        : "=r"((r)[0]), "=r"((r)[1]), "=r"((r)[2]), "=r"((r)[3]) : "r"(addr))

#define CP_ASYNC16(dst, src) \
    asm volatile("cp.async.cg.shared.global [%0], [%1], 16;" :: "r"(dst), "l"(src) : "memory")
#define CP_ASYNC4(dst, src) \
    asm volatile("cp.async.ca.shared.global [%0], [%1], 4;" :: "r"(dst), "l"(src) : "memory")
#define CP_COMMIT() asm volatile("cp.async.commit_group;" ::: "memory")
#define CP_WAIT0()  asm volatile("cp.async.wait_group 0;" ::: "memory")

__device__ __forceinline__ uint32_t smem_u32(const void* p) {
    uint32_t a;
    asm("{ .reg .u64 t; cvta.to.shared.u64 t, %1; cvt.u32.u64 %0, t; }" : "=r"(a) : "l"(p));
    return a;
}

// ---------------- device scratch ----------------
__device__ float g_xx[Bn * Nn];
__device__ int   g_idx[Bn * Nn * KNN];
__device__ float g_u[Bn * Nn * On];
__device__ float g_v[Bn * Nn * On];
__device__ float g_sel[Bn * Nn * On];
__device__ float g_sum[On];
__device__ float g_sumsq[On];
__device__ float g_cA[On];
__device__ float g_cB[On];
__device__ __half g_s[Bn * Nn * 128];   // [b][n][h0(64)|h1(64)] fp16 splits

// ---------------- K1: squared norms ----------------
__global__ void xx_kernel(const float* __restrict__ x) {
    int i = blockIdx.x * 256 + threadIdx.x;
    int b = i >> 12;
    int n = i & (Nn - 1);
    const float* xp = x + b * Cn * Nn + n;
    float s = 0.f;
#pragma unroll
    for (int c = 0; c < Cn; ++c) { float v = xp[c * Nn]; s = fmaf(v, v, s); }
    g_xx[i] = s;
}

// ---------------- K1b: fp16x2 split + transpose ----------------
__global__ void split_kernel(const float* __restrict__ x) {
    __shared__ alignas(16) __half sb0[64 * 72];
    __shared__ alignas(16) __half sb1[64 * 72];

    int t = threadIdx.x;
    int b = blockIdx.x >> 6;
    int n0 = (blockIdx.x & 63) * 64;

#pragma unroll
    for (int j = 0; j < 16; ++j) {
        int idx = j * 256 + t;
        int c = idx >> 6, n = idx & 63;
        float v = x[b * Cn * Nn + c * Nn + n0 + n];
        __half h0 = __float2half_rn(v);
        __half h1 = __float2half_rn(v - __half2float(h0));
        sb0[n * 72 + c] = h0;
        sb1[n * 72 + c] = h1;
    }
    __syncthreads();

    uint4* g4 = (uint4*)g_s;
#pragma unroll
    for (int j = 0; j < 4; ++j) {
        int idx = j * 256 + t;
        int r = idx >> 4, u = idx & 15;
        int ch = u >> 3, c8 = (u & 7) * 8;
        const __half* src = ch ? sb1 : sb0;
        g4[(b * Nn + n0 + r) * 16 + u] = *(const uint4*)(src + r * 72 + c8);
    }
}

// ---------------- K2: fp16x2 mma.sync, 3 CTAs/SM, gated top-K ----------------
#define QT 64
#define CT 64
#define SROW 272
#define BTILE 17408

#define OFF_A    0                      // 17408
#define OFF_B    17408                  // 2 x 17408 -> 52224
#define OFF_HXX  52224                  // 2 x 64 f  -> 52736
#define OFF_STG  52736                  // 8 warps x 32 owners x 20 f -> 73216
#define OFF_MINV 73216                  // -> 74240
#define SMEM_KNN 74240
#define OFF_MV   0                      // post-loop alias
#define OFF_MI   20480                  // post-loop alias

__global__ void __launch_bounds__(256, 3) knn_kernel() {
    extern __shared__ char sm[];
    uint32_t smb = smem_u32(sm);
    float* s_hxx  = (float*)(sm + OFF_HXX);
    float* s_minv = (float*)(sm + OFF_MINV);
    float* s_mv   = (float*)(sm + OFF_MV);
    int*   s_mi   = (int*)  (sm + OFF_MI);

    int t = threadIdx.x, w = t >> 5, lane = t & 31;
    int g = lane >> 2, q4 = lane & 3;
    int b = blockIdx.x >> 6;
    int n0 = (blockIdx.x & 63) * QT;

    int wrow = (w & 3) * 16;
    int ntb  = (w >= 4) ? 4 : 0;

    const uint4* gs4 = (const uint4*)g_s;
    int lr = t >> 2, lu = t & 3;
    const uint4* gA = gs4 + (size_t)(b * Nn + n0 + lr) * 16 + lu;
    const uint4* gB = gs4 + (size_t)(b * Nn + lr) * 16 + lu;
    uint32_t dstA = (uint32_t)(OFF_A + lr * SROW + lu * 16);
    uint32_t dstB = (uint32_t)(OFF_B + lr * SROW + lu * 16);
#pragma unroll
    for (int j = 0; j < 4; ++j) {
        *(uint4*)(sm + dstA + j * 64) = gA[j * 4];
        *(uint4*)(sm + dstB + j * 64) = gB[j * 4];
    }
    gB += CT * 16;
    const float* gxxp = g_xx + b * Nn + t;
    if (t < CT) s_hxx[t] = gxxp[0];
    s_minv[t] = -INFINITY;
    __syncthreads();

    uint32_t aaddr = smb + OFF_A
        + (uint32_t)((wrow + ((lane >> 3) & 1) * 8 + (lane & 7)) * SROW)
        + (uint32_t)((lane >> 4) * 16);
    uint32_t brow = (uint32_t)(ntb * 8 + (lane >> 4) * 8 + (lane & 7));
    uint32_t bk   = (uint32_t)(((lane >> 3) & 1) * 16);
    uint32_t baddr0 = smb + OFF_B + brow * SROW + bk;

    float* stg = (float*)(sm + OFF_STG) + w * 640;
    int og0 = (g * 2 + (q4 >> 1)) * 20;
    int og1 = ((g + 8) * 2 + (q4 >> 1)) * 20;
    int slot0 = (q4 & 1) * 2;
    int rbase = (wrow + (lane >> 1)) * 4;
    int mvslot = rbase + (ntb ? 2 : 0) + (lane & 1);
    int hxb = ntb * 8 + 2 * q4;
    const float* mystg = stg + lane * 20;

    float vals[KNN];
    int   idxs[KNN];
#pragma unroll
    for (int j = 0; j < KNN; ++j) { vals[j] = -INFINITY; idxs[j] = 0x7fffffff; }

    for (int ti = 0; ti < Nn / CT; ++ti) {
        int buf = ti & 1;
        if (ti < Nn / CT - 1) {
            uint32_t d = smb + dstB + (uint32_t)((buf ^ 1) * BTILE);
            const char* gsrc = (const char*)gB;
#pragma unroll
            for (int j = 0; j < 4; ++j)
                CP_ASYNC16(d + j * 64, gsrc + j * 64);
            gB += CT * 16;
            if (t < CT) {
                uint32_t hd = smb + (uint32_t)(OFF_HXX + ((buf ^ 1) * 64 + t) * 4);
                CP_ASYNC4(hd, gxxp + (ti + 1) * CT);
            }
            CP_COMMIT();
        }

        // ---- MMA: sequential col-halves to halve B-frag register liveness ----
        uint32_t ba = baddr0 + (uint32_t)(buf * BTILE);
        float acc[4][4];
#pragma unroll
        for (int nt = 0; nt < 4; ++nt)
#pragma unroll
            for (int e = 0; e < 4; ++e) acc[nt][e] = 0.f;

#pragma unroll
        for (int ks = 0; ks < 4; ++ks) {
            uint32_t ak = aaddr + ks * 32;
            uint32_t a0[4], a1[4];
            LDM_X4(a0, ak);                 // h0
            LDM_X4(a1, ak + 128);           // h1
            {   // cols 0-15 of this warp's half
                uint32_t bb = ba + ks * 32;
                uint32_t g0[4], g1[4];
                LDM_X4(g0, bb);
                LDM_X4(g1, bb + 128);
                MMA_F16(acc[0], a0, g0[0], g0[1]); MMA_F16(acc[1], a0, g0[2], g0[3]);
                MMA_F16(acc[0], a1, g1[0], g1[1]); MMA_F16(acc[1], a1, g1[2], g1[3]);
                MMA_F16(acc[0], a0, g1[0], g1[1]); MMA_F16(acc[1], a0, g1[2], g1[3]);
                MMA_F16(acc[0], a1, g0[0], g0[1]); MMA_F16(acc[1], a1, g0[2], g0[3]);
            }
            {   // cols 16-31 of this warp's half
                uint32_t bb = ba + 16 * SROW + ks * 32;
                uint32_t g0[4], g1[4];
                LDM_X4(g0, bb);
                LDM_X4(g1, bb + 128);
                MMA_F16(acc[2], a0, g0[0], g0[1]); MMA_F16(acc[3], a0, g0[2], g0[3]);
                MMA_F16(acc[2], a1, g1[0], g1[1]); MMA_F16(acc[3], a1, g1[2], g1[3]);
                MMA_F16(acc[2], a0, g1[0], g1[1]); MMA_F16(acc[3], a0, g1[2], g1[3]);
                MMA_F16(acc[2], a1, g0[0], g0[1]); MMA_F16(acc[3], a1, g0[2], g0[3]);
            }
        }

        // ---- stage (score = I - 0.5*xx), warp-local ----
#pragma unroll
        for (int nt = 0; nt < 4; ++nt) {
            float2 hx = *(const float2*)(s_hxx + buf * 64 + hxb + nt * 8);
            *(float2*)(stg + og0 + nt * 4 + slot0) =
                make_float2(fmaf(-0.5f, hx.x, acc[nt][0]), fmaf(-0.5f, hx.y, acc[nt][1]));
            *(float2*)(stg + og1 + nt * 4 + slot0) =
                make_float2(fmaf(-0.5f, hx.x, acc[nt][2]), fmaf(-0.5f, hx.y, acc[nt][3]));
        }
        __syncwarp();

        // ---- owner scan ----
        const float4* sp = (const float4*)mystg;
        float4 v0 = sp[0], v1 = sp[1], v2 = sp[2], v3 = sp[3];
        float tmax = fmaxf(
            fmaxf(fmaxf(fmaxf(v0.x, v0.y), fmaxf(v0.z, v0.w)),
                  fmaxf(fmaxf(v1.x, v1.y), fmaxf(v1.z, v1.w))),
            fmaxf(fmaxf(fmaxf(v2.x, v2.y), fmaxf(v2.z, v2.w)),
                  fmaxf(fmaxf(v3.x, v3.y), fmaxf(v3.z, v3.w))));
        float thr = fmaxf(fmaxf(s_minv[rbase], s_minv[rbase + 1]),
                          fmaxf(s_minv[rbase + 2], s_minv[rbase + 3]));
        float thr_eff = fmaxf(thr, vals[KNN - 1]);
        if (tmax > thr_eff) {
            unsigned qm = 0;
            qm |= (v0.x > thr_eff) ? 0x0001u : 0u;
            qm |= (v0.y > thr_eff) ? 0x0002u : 0u;
            qm |= (v0.z > thr_eff) ? 0x0004u : 0u;
            qm |= (v0.w > thr_eff) ? 0x0008u : 0u;
            qm |= (v1.x > thr_eff) ? 0x0010u : 0u;
            qm |= (v1.y > thr_eff) ? 0x0020u : 0u;
            qm |= (v1.z > thr_eff) ? 0x0040u : 0u;
            qm |= (v1.w > thr_eff) ? 0x0080u : 0u;
            qm |= (v2.x > thr_eff) ? 0x0100u : 0u;
            qm |= (v2.y > thr_eff) ? 0x0200u : 0u;
            qm |= (v2.z > thr_eff) ? 0x0400u : 0u;
            qm |= (v2.w > thr_eff) ? 0x0800u : 0u;
            qm |= (v3.x > thr_eff) ? 0x1000u : 0u;
            qm |= (v3.y > thr_eff) ? 0x2000u : 0u;
            qm |= (v3.z > thr_eff) ? 0x4000u : 0u;
            qm |= (v3.w > thr_eff) ? 0x8000u : 0u;

            int mbase = ti * CT + ntb * 8 + 4 * (lane & 1);
            while (qm) {
                int j = __ffs(qm) - 1;
                qm &= qm - 1;
                float v = mystg[j];
                if (v > vals[KNN - 1] && v > thr) {
                    vals[KNN - 1] = v;
                    idxs[KNN - 1] = mbase + ((j >> 2) << 3) + (j & 3);
#pragma unroll
                    for (int q = KNN - 1; q > 0; --q) {
                        bool sw = vals[q] > vals[q - 1];
                        float tv = sw ? vals[q - 1] : vals[q];
                        float tu = sw ? vals[q]     : vals[q - 1];
                        int   ta = sw ? idxs[q - 1] : idxs[q];
                        int   tb = sw ? idxs[q]     : idxs[q - 1];
                        vals[q] = tv; vals[q - 1] = tu;
                        idxs[q] = ta; idxs[q - 1] = tb;
                    }
                }
            }
            s_minv[mvslot] = vals[KNN - 1];
        }
        CP_WAIT0();
        __syncthreads();
    }

    // ---- dump lists, 4-way merge per row ----
    int owner_id = rbase + (ntb ? 2 : 0) + (lane & 1);
#pragma unroll
    for (int j = 0; j < KNN; ++j) {
        s_mv[owner_id * KNN + j] = vals[j];
        s_mi[owner_id * KNN + j] = idxs[j];
    }
    __syncthreads();

    if (t < QT) {
        int head[4] = {0, 0, 0, 0};
        int lb = t * 4;
        int obase = (b * Nn + n0 + t) * KNN;
        for (int kk = 0; kk < KNN; ++kk) {
            float bv = -INFINITY; int bi = 0x7fffffff; int bs = 0;
#pragma unroll
            for (int s = 0; s < 4; ++s) {
                int h = head[s];
                if (h < KNN) {
                    float v  = s_mv[(lb + s) * KNN + h];
                    int   im = s_mi[(lb + s) * KNN + h];
                    if (v > bv || (v == bv && im < bi)) { bv = v; bi = im; bs = s; }
                }
            }
            g_idx[obase + kk] = bi;
            head[bs]++;
        }
    }
}

// ---------------- K3: projections ----------------
__global__ void proj_kernel(const float* __restrict__ x, const float* __restrict__ W) {
    __shared__ float s_w1[Cn][On];
    __shared__ float s_wd[Cn][On];
    __shared__ float s_x[Cn][32];

    int t = threadIdx.x;
    for (int i = t; i < On * Cn; i += 256) {
        int o = i / Cn, c = i % Cn;
        float w1 = W[o * (2 * Cn) + c];
        float w2 = W[o * (2 * Cn) + Cn + c];
        s_w1[c][o] = w1;
        s_wd[c][o] = w2 - w1;
    }
    int b  = blockIdx.x / (Nn / 32);
    int n0 = (blockIdx.x % (Nn / 32)) * 32;
    for (int i = t; i < Cn * 32; i += 256) {
        int c = i / 32, p = i % 32;
        s_x[c][p] = x[b * Cn * Nn + c * Nn + n0 + p];
    }
    __syncthreads();

    int warp = t >> 5, lane = t & 31;
    int p0 = warp * 4;
    float au0[4] = {0,0,0,0}, au1[4] = {0,0,0,0};
    float av0[4] = {0,0,0,0}, av1[4] = {0,0,0,0};

#pragma unroll 8
    for (int c = 0; c < Cn; ++c) {
        float w1l = s_w1[c][lane], w1h = s_w1[c][lane + 32];
        float wdl = s_wd[c][lane], wdh = s_wd[c][lane + 32];
#pragma unroll
        for (int pp = 0; pp < 4; ++pp) {
            float xv = s_x[c][p0 + pp];
            au0[pp] = fmaf(xv, w1l, au0[pp]);
            au1[pp] = fmaf(xv, w1h, au1[pp]);
            av0[pp] = fmaf(xv, wdl, av0[pp]);
            av1[pp] = fmaf(xv, wdh, av1[pp]);
        }
    }
#pragma unroll
    for (int pp = 0; pp < 4; ++pp) {
        int pt = b * Nn + n0 + p0 + pp;
        g_u[pt * On + lane]      = au0[pp];
        g_u[pt * On + 32 + lane] = au1[pp];
        g_v[pt * On + lane]      = av0[pp];
        g_v[pt * On + 32 + lane] = av1[pp];
    }
}

// ---------------- K0: zero stats ----------------
__global__ void zero_kernel() {
    int t = threadIdx.x;
    if (t < On) { g_sum[t] = 0.f; g_sumsq[t] = 0.f; }
}

// ---------------- K4: gather, max/min over k, stats ----------------
__global__ void maxstats_kernel(const float* __restrict__ gamma) {
    __shared__ float ssum[8][On];
    __shared__ float ssq[8][On];
    int warp = threadIdx.x >> 5, lane = threadIdx.x & 31;
    int pt = blockIdx.x * 8 + warp;
    int b = pt >> 12;

    const float* vp = g_v + pt * On;
    float v0 = vp[lane], v1 = vp[lane + 32];
    float mx0 = -INFINITY, mx1 = -INFINITY, mn0 = INFINITY, mn1 = INFINITY;
    float s0 = 0.f, s1 = 0.f, q0 = 0.f, q1 = 0.f;
    const int* ip = g_idx + pt * KNN;

#pragma unroll
    for (int k = 0; k < KNN; ++k) {
        int m = ip[k];
        const float* up = g_u + ((b << 12) + m) * On;
        float y0 = up[lane] + v0;
        float y1 = up[lane + 32] + v1;
        mx0 = fmaxf(mx0, y0); mn0 = fminf(mn0, y0);
        mx1 = fmaxf(mx1, y1); mn1 = fminf(mn1, y1);
        s0 += y0; q0 = fmaf(y0, y0, q0);
        s1 += y1; q1 = fmaf(y1, y1, q1);
    }
    float g0 = gamma[lane], g1 = gamma[lane + 32];
    g_sel[pt * On + lane]      = (g0 >= 0.f) ? mx0 : mn0;
    g_sel[pt * On + 32 + lane] = (g1 >= 0.f) ? mx1 : mn1;

    ssum[warp][lane] = s0; ssum[warp][lane + 32] = s1;
    ssq[warp][lane]  = q0; ssq[warp][lane + 32]  = q1;
    __syncthreads();
    if (threadIdx.x < On) {
        float ts = 0.f, tq = 0.f;
#pragma unroll
        for (int w = 0; w < 8; ++w) { ts += ssum[w][threadIdx.x]; tq += ssq[w][threadIdx.x]; }
        atomicAdd(&g_sum[threadIdx.x], ts);
        atomicAdd(&g_sumsq[threadIdx.x], tq);
    }
}

// ---------------- K6: BN coefficients ----------------
__global__ void bnfinal_kernel(const float* __restrict__ gamma, const float* __restrict__ beta) {
    int o = threadIdx.x;
    if (o < On) {
        const float M = (float)(Bn * Nn * KNN);
        float mean = g_sum[o] / M;
        float var  = g_sumsq[o] / M - mean * mean;
        var = fmaxf(var, 0.f);
        float a = gamma[o] * rsqrtf(var + EPSC);
        g_cA[o] = a;
        g_cB[o] = beta[o] - mean * a;
    }
}

// ---------------- K7: finalize + transpose ----------------
__global__ void finalize_kernel(float* __restrict__ out) {
    __shared__ float tile[32][On + 1];
    __shared__ float sA[On], sB[On];
    int t = threadIdx.x;
    int b  = blockIdx.x / (Nn / 32);
    int n0 = (blockIdx.x % (Nn / 32)) * 32;
    if (t < On) { sA[t] = g_cA[t]; sB[t] = g_cB[t]; }
    for (int i = t; i < 32 * On; i += 256) {
        int nl = i / On, o = i % On;
        tile[nl][o] = g_sel[(b * Nn + n0) * On + i];
    }
    __syncthreads();
    for (int i = t; i < 32 * On; i += 256) {
        int o = i / 32, nl = i % 32;
        float y = tile[nl][o];
        float val = fmaf(sA[o], y, sB[o]);
        out[b * On * Nn + o * Nn + n0 + nl] = (val >= 0.f) ? val : SLOPE * val;
    }
}

// ---------------- launch ----------------
// knn at position 4 (harness ncu -s 5 -c 1 lands there).
extern "C" void kernel_launch(void* const* d_in, const int* in_sizes, int n_in,
                              void* d_out, int out_size) {
    const float* x     = (const float*)d_in[0];
    const float* W     = (const float*)d_in[1];
    const float* gamma = (const float*)d_in[2];
    const float* beta  = (const float*)d_in[3];
    float* out = (float*)d_out;

    cudaFuncSetAttribute(knn_kernel, cudaFuncAttributeMaxDynamicSharedMemorySize, SMEM_KNN);

    xx_kernel<<<(Bn * Nn) / 256, 256>>>(x);
    split_kernel<<<Bn * (Nn / 64), 256>>>(x);
    proj_kernel<<<Bn * (Nn / 32), 256>>>(x, W);
    knn_kernel<<<Bn * (Nn / QT), 256, SMEM_KNN>>>();
    zero_kernel<<<1, 64>>>();
    maxstats_kernel<<<(Bn * Nn) / 8, 256>>>(gamma);
    bnfinal_kernel<<<1, 64>>>(gamma, beta);
    finalize_kernel<<<Bn * (Nn / 32), 256>>>(out);
}